// round 2
// baseline (speedup 1.0000x reference)
#include <cuda_runtime.h>
#include <cuda_bf16.h>
#include <math.h>

#define HIDDEN   1024
#define HEADS    16
#define HEAD_DIM 64
#define MLPH     4096
#define BB       2
#define LL       2048
#define NTOK     (BB*LL)          // 4096
#define W1N      (3*HIDDEN+MLPH)  // 7168

// ---------------- scratch (static device globals; no runtime alloc) ------------
__device__ float g_mod[BB*3*HIDDEN];        // shift|scale|gate per batch
__device__ float g_xmod[NTOK*HIDDEN];       // modulated LN output
__device__ float g_h[(size_t)NTOK*W1N];     // qkv(3072) | mlp(4096)
__device__ float g_y[(size_t)NTOK*2*HIDDEN];// attn(1024) | tanh-mlp(1024)

// ---------------- kernel 1: mod = silu(vec) @ w_mod + b_mod --------------------
__global__ void mod_kernel(const float* __restrict__ vec,
                           const float* __restrict__ w_mod,
                           const float* __restrict__ b_mod,
                           float* __restrict__ mod) {
    __shared__ float sv[HIDDEN];
    int b = blockIdx.y;
    int n = blockIdx.x * 128 + threadIdx.x;
    for (int i = threadIdx.x; i < HIDDEN; i += 128) {
        float v = vec[b*HIDDEN + i];
        sv[i] = v / (1.0f + expf(-v));
    }
    __syncthreads();
    float acc = b_mod[n];
    #pragma unroll 8
    for (int k = 0; k < HIDDEN; k++)
        acc = fmaf(sv[k], w_mod[(size_t)k*3*HIDDEN + n], acc);
    mod[b*3*HIDDEN + n] = acc;
}

// ---------------- kernel 2: layernorm + modulate -------------------------------
__global__ void __launch_bounds__(256) ln_mod_kernel(const float* __restrict__ x,
                                                     const float* __restrict__ mod,
                                                     float* __restrict__ xmod) {
    __shared__ float sbuf[8];
    __shared__ float s_mean, s_rstd;
    int token = blockIdx.x;
    int b = token >> 11;
    int tid = threadIdx.x;
    const float4 xv = ((const float4*)(x + (size_t)token*HIDDEN))[tid];

    // mean
    float s = xv.x + xv.y + xv.z + xv.w;
    #pragma unroll
    for (int o = 16; o > 0; o >>= 1) s += __shfl_xor_sync(0xffffffffu, s, o);
    if ((tid & 31) == 0) sbuf[tid >> 5] = s;
    __syncthreads();
    if (tid == 0) {
        float t = 0;
        #pragma unroll
        for (int i = 0; i < 8; i++) t += sbuf[i];
        s_mean = t * (1.0f / HIDDEN);
    }
    __syncthreads();
    float m = s_mean;
    float dx = xv.x - m, dy = xv.y - m, dz = xv.z - m, dw = xv.w - m;
    float ss = dx*dx + dy*dy + dz*dz + dw*dw;
    #pragma unroll
    for (int o = 16; o > 0; o >>= 1) ss += __shfl_xor_sync(0xffffffffu, ss, o);
    __syncthreads();
    if ((tid & 31) == 0) sbuf[tid >> 5] = ss;
    __syncthreads();
    if (tid == 0) {
        float t = 0;
        #pragma unroll
        for (int i = 0; i < 8; i++) t += sbuf[i];
        s_rstd = rsqrtf(t * (1.0f / HIDDEN) + 1e-6f);
    }
    __syncthreads();
    float r = s_rstd;
    int c = tid * 4;
    const float4 sh = *(const float4*)(mod + b*3*HIDDEN + c);
    const float4 sc = *(const float4*)(mod + b*3*HIDDEN + HIDDEN + c);
    float4 o4;
    o4.x = fmaf(1.0f + sc.x, dx*r, sh.x);
    o4.y = fmaf(1.0f + sc.y, dy*r, sh.y);
    o4.z = fmaf(1.0f + sc.z, dz*r, sh.z);
    o4.w = fmaf(1.0f + sc.w, dw*r, sh.w);
    ((float4*)(xmod + (size_t)token*HIDDEN))[tid] = o4;
}

// ---------------- kernel 3: generic tiled SGEMM, 128x128x8, 8x8 microtile ------
// MODE 0: C = A@B + bias
// MODE 1: C = tanh(A@B + bias)
// MODE 2: C = x + gate * (A@B + bias)    (gate = mod[batch][2048+n])
template<int MODE>
__global__ void __launch_bounds__(256) sgemm_kernel(
        const float* __restrict__ A, int lda,
        const float* __restrict__ B, int ldb,
        float* __restrict__ C, int ldc,
        int K,
        const float* __restrict__ bias,
        const float* __restrict__ xres,
        const float* __restrict__ mod) {
    __shared__ float As[8][128];
    __shared__ float Bs[8][128];
    const int bm = blockIdx.y * 128;
    const int bn = blockIdx.x * 128;
    const int tid = threadIdx.x;
    const int arow = tid >> 1, acol = (tid & 1) * 4;
    const int brow = tid >> 5, bcol = (tid & 31) * 4;
    const int tr = (tid >> 4) * 8, tc = (tid & 15) * 8;

    float acc[8][8];
    #pragma unroll
    for (int i = 0; i < 8; i++)
        #pragma unroll
        for (int j = 0; j < 8; j++) acc[i][j] = 0.0f;

    for (int k0 = 0; k0 < K; k0 += 8) {
        float4 a4 = *(const float4*)(A + (size_t)(bm + arow)*lda + k0 + acol);
        As[acol+0][arow] = a4.x;
        As[acol+1][arow] = a4.y;
        As[acol+2][arow] = a4.z;
        As[acol+3][arow] = a4.w;
        *(float4*)&Bs[brow][bcol] =
            *(const float4*)(B + (size_t)(k0 + brow)*ldb + bn + bcol);
        __syncthreads();
        #pragma unroll
        for (int kk = 0; kk < 8; kk++) {
            float ar[8], br[8];
            *(float4*)(ar)   = *(float4*)&As[kk][tr];
            *(float4*)(ar+4) = *(float4*)&As[kk][tr+4];
            *(float4*)(br)   = *(float4*)&Bs[kk][tc];
            *(float4*)(br+4) = *(float4*)&Bs[kk][tc+4];
            #pragma unroll
            for (int i = 0; i < 8; i++)
                #pragma unroll
                for (int j = 0; j < 8; j++)
                    acc[i][j] = fmaf(ar[i], br[j], acc[i][j]);
        }
        __syncthreads();
    }

    #pragma unroll
    for (int i = 0; i < 8; i++) {
        int m = bm + tr + i;
        float* crow = C + (size_t)m*ldc + bn + tc;
        float v[8];
        #pragma unroll
        for (int j = 0; j < 8; j++) v[j] = acc[i][j] + bias[bn + tc + j];
        if (MODE == 1) {
            #pragma unroll
            for (int j = 0; j < 8; j++) v[j] = tanhf(v[j]);
        } else if (MODE == 2) {
            int b = m >> 11;
            const float* gp = mod + b*3*HIDDEN + 2*HIDDEN + bn + tc;
            const float* xp = xres + (size_t)m*HIDDEN + bn + tc;
            #pragma unroll
            for (int j = 0; j < 8; j++) v[j] = fmaf(gp[j], v[j], xp[j]);
        }
        *(float4*)(crow)   = *(float4*)(v);
        *(float4*)(crow+4) = *(float4*)(v+4);
    }
}

// ---------------- kernel 4: per-head RMSNorm + RoPE on q,k (in place) ----------
__global__ void __launch_bounds__(512) qk_norm_rope_kernel(
        float* __restrict__ h,
        const float* __restrict__ pe,
        const float* __restrict__ q_scale,
        const float* __restrict__ k_scale) {
    int token = blockIdx.x;
    int l = token & (LL - 1);
    int head = threadIdx.x >> 5;
    int lane = threadIdx.x & 31;      // pair index 0..31

    float* qp = h + (size_t)token*W1N + head*HEAD_DIM;
    float* kp = qp + HIDDEN;

    const float4 p = *(const float4*)(pe + (size_t)l*128 + lane*4);
    float sx = q_scale[lane*2], sy = q_scale[lane*2+1];
    float kx = k_scale[lane*2], ky = k_scale[lane*2+1];

    // q
    {
        float2 q2 = *(float2*)(qp + lane*2);
        float ss = q2.x*q2.x + q2.y*q2.y;
        #pragma unroll
        for (int o = 16; o > 0; o >>= 1) ss += __shfl_xor_sync(0xffffffffu, ss, o);
        float rr = rsqrtf(ss * (1.0f/HEAD_DIM) + 1e-6f);
        float t0 = q2.x * rr * sx, t1 = q2.y * rr * sy;
        float2 o2;
        o2.x = p.x*t0 + p.y*t1;
        o2.y = p.z*t0 + p.w*t1;
        *(float2*)(qp + lane*2) = o2;
    }
    // k
    {
        float2 k2 = *(float2*)(kp + lane*2);
        float ss = k2.x*k2.x + k2.y*k2.y;
        #pragma unroll
        for (int o = 16; o > 0; o >>= 1) ss += __shfl_xor_sync(0xffffffffu, ss, o);
        float rr = rsqrtf(ss * (1.0f/HEAD_DIM) + 1e-6f);
        float t0 = k2.x * rr * kx, t1 = k2.y * rr * ky;
        float2 o2;
        o2.x = p.x*t0 + p.y*t1;
        o2.y = p.z*t0 + p.w*t1;
        *(float2*)(kp + lane*2) = o2;
    }
}

// ---------------- kernel 5: flash attention (fp32) -----------------------------
// grid: (L/64 q-tiles, B*HEADS). block: 256 threads.
__global__ void __launch_bounds__(256) attn_kernel(const float* __restrict__ h,
                                                   float* __restrict__ y) {
    __shared__ float Qs[64][68];
    __shared__ float Ks[32][68];
    __shared__ float Vs[32][68];
    __shared__ float Ss[64][33];
    __shared__ float m_sm[64], l_sm[64], f_sm[64];

    const int tid = threadIdx.x;
    const int bh = blockIdx.y;
    const int b = bh >> 4, hd = bh & 15;
    const int q0 = blockIdx.x << 6;
    const float* base = h + (size_t)b*LL*W1N + hd*HEAD_DIM;

    // load Q tile (64 x 64)
    for (int i = tid; i < 1024; i += 256) {
        int r = i >> 4, c = (i & 15) << 2;
        *(float4*)&Qs[r][c] = *(const float4*)(base + (size_t)(q0 + r)*W1N + c);
    }
    if (tid < 64) { m_sm[tid] = -1e30f; l_sm[tid] = 0.0f; }

    float o[16];
    #pragma unroll
    for (int i = 0; i < 16; i++) o[i] = 0.0f;
    const int ro = tid >> 2, dg = (tid & 3) << 4;   // O ownership
    const int r2 = tid >> 3, kl = tid & 7;          // score ownership
    __syncthreads();

    for (int kt = 0; kt < LL/32; kt++) {
        int krow0 = kt << 5;
        for (int i = tid; i < 512; i += 256) {
            int r = i >> 4, c = (i & 15) << 2;
            const float* kp = base + HIDDEN + (size_t)(krow0 + r)*W1N + c;
            *(float4*)&Ks[r][c] = *(const float4*)kp;
            *(float4*)&Vs[r][c] = *(const float4*)(kp + HIDDEN);
        }
        __syncthreads();

        // scores: 2 rows x 4 keys per thread
        float a0[4] = {0,0,0,0}, a1[4] = {0,0,0,0};
        #pragma unroll
        for (int d = 0; d < 64; d += 4) {
            float4 qa = *(float4*)&Qs[r2][d];
            float4 qb = *(float4*)&Qs[r2+32][d];
            #pragma unroll
            for (int j = 0; j < 4; j++) {
                float4 k4 = *(float4*)&Ks[kl + (j<<3)][d];
                a0[j] += qa.x*k4.x + qa.y*k4.y + qa.z*k4.z + qa.w*k4.w;
                a1[j] += qb.x*k4.x + qb.y*k4.y + qb.z*k4.z + qb.w*k4.w;
            }
        }
        #pragma unroll
        for (int j = 0; j < 4; j++) {
            Ss[r2][kl + (j<<3)]    = a0[j] * 0.125f;
            Ss[r2+32][kl + (j<<3)] = a1[j] * 0.125f;
        }
        __syncthreads();

        // online softmax per row
        if (tid < 64) {
            float mo = m_sm[tid];
            float mx = mo;
            #pragma unroll
            for (int k = 0; k < 32; k++) mx = fmaxf(mx, Ss[tid][k]);
            float f = __expf(mo - mx);
            float s = 0.0f;
            #pragma unroll
            for (int k = 0; k < 32; k++) {
                float pv = __expf(Ss[tid][k] - mx);
                Ss[tid][k] = pv;
                s += pv;
            }
            m_sm[tid] = mx;
            l_sm[tid] = l_sm[tid]*f + s;
            f_sm[tid] = f;
        }
        __syncthreads();

        // O accumulation
        float f = f_sm[ro];
        #pragma unroll
        for (int i = 0; i < 16; i++) o[i] *= f;
        #pragma unroll
        for (int k = 0; k < 32; k++) {
            float pv = Ss[ro][k];
            float4 v0 = *(float4*)&Vs[k][dg];
            float4 v1 = *(float4*)&Vs[k][dg+4];
            float4 v2 = *(float4*)&Vs[k][dg+8];
            float4 v3 = *(float4*)&Vs[k][dg+12];
            o[0]  = fmaf(pv, v0.x, o[0]);  o[1]  = fmaf(pv, v0.y, o[1]);
            o[2]  = fmaf(pv, v0.z, o[2]);  o[3]  = fmaf(pv, v0.w, o[3]);
            o[4]  = fmaf(pv, v1.x, o[4]);  o[5]  = fmaf(pv, v1.y, o[5]);
            o[6]  = fmaf(pv, v1.z, o[6]);  o[7]  = fmaf(pv, v1.w, o[7]);
            o[8]  = fmaf(pv, v2.x, o[8]);  o[9]  = fmaf(pv, v2.y, o[9]);
            o[10] = fmaf(pv, v2.z, o[10]); o[11] = fmaf(pv, v2.w, o[11]);
            o[12] = fmaf(pv, v3.x, o[12]); o[13] = fmaf(pv, v3.y, o[13]);
            o[14] = fmaf(pv, v3.z, o[14]); o[15] = fmaf(pv, v3.w, o[15]);
        }
        __syncthreads();
    }

    float inv = 1.0f / l_sm[ro];
    float* yp = y + (size_t)(b*LL + q0 + ro)*(2*HIDDEN) + hd*HEAD_DIM + dg;
    float4 w0, w1, w2, w3;
    w0.x=o[0]*inv;  w0.y=o[1]*inv;  w0.z=o[2]*inv;  w0.w=o[3]*inv;
    w1.x=o[4]*inv;  w1.y=o[5]*inv;  w1.z=o[6]*inv;  w1.w=o[7]*inv;
    w2.x=o[8]*inv;  w2.y=o[9]*inv;  w2.z=o[10]*inv; w2.w=o[11]*inv;
    w3.x=o[12]*inv; w3.y=o[13]*inv; w3.z=o[14]*inv; w3.w=o[15]*inv;
    *(float4*)(yp)    = w0;
    *(float4*)(yp+4)  = w1;
    *(float4*)(yp+8)  = w2;
    *(float4*)(yp+12) = w3;
}

// ---------------- launch --------------------------------------------------------
extern "C" void kernel_launch(void* const* d_in, const int* in_sizes, int n_in,
                              void* d_out, int out_size) {
    const float* x       = (const float*)d_in[0];
    const float* vec     = (const float*)d_in[1];
    const float* pe      = (const float*)d_in[2];
    const float* w_mod   = (const float*)d_in[3];
    const float* b_mod   = (const float*)d_in[4];
    const float* w1      = (const float*)d_in[5];
    const float* b1      = (const float*)d_in[6];
    const float* w_mlp   = (const float*)d_in[7];
    const float* b_mlp   = (const float*)d_in[8];
    const float* w2      = (const float*)d_in[9];
    const float* b2      = (const float*)d_in[10];
    const float* q_scale = (const float*)d_in[11];
    const float* k_scale = (const float*)d_in[12];
    float* out = (float*)d_out;

    float *mod, *xmod, *h, *y;
    cudaGetSymbolAddress((void**)&mod,  g_mod);
    cudaGetSymbolAddress((void**)&xmod, g_xmod);
    cudaGetSymbolAddress((void**)&h,    g_h);
    cudaGetSymbolAddress((void**)&y,    g_y);

    // 1. modulation vector
    mod_kernel<<<dim3(3*HIDDEN/128, BB), 128>>>(vec, w_mod, b_mod, mod);
    // 2. layernorm + modulate
    ln_mod_kernel<<<NTOK, 256>>>(x, mod, xmod);
    // 3. h = x_mod @ w1 + b1   (4096 x 7168, K=1024)
    sgemm_kernel<0><<<dim3(W1N/128, NTOK/128), 256>>>(
        xmod, HIDDEN, w1, W1N, h, W1N, HIDDEN, b1, nullptr, nullptr);
    // 4. q,k rmsnorm + rope in place
    qk_norm_rope_kernel<<<NTOK, 512>>>(h, pe, q_scale, k_scale);
    // 5. attention -> y[:, :1024]
    attn_kernel<<<dim3(LL/64, BB*HEADS), 256>>>(h, y);
    // 6. y[:, 1024:] = tanh(mlp @ w_mlp + b_mlp)   (4096 x 1024, K=4096)
    sgemm_kernel<1><<<dim3(HIDDEN/128, NTOK/128), 256>>>(
        h + 3*HIDDEN, W1N, w_mlp, HIDDEN, y + HIDDEN, 2*HIDDEN,
        MLPH, b_mlp, nullptr, nullptr);
    // 7. out = x + gate * (y @ w2 + b2)   (4096 x 1024, K=2048)
    sgemm_kernel<2><<<dim3(HIDDEN/128, NTOK/128), 256>>>(
        y, 2*HIDDEN, w2, HIDDEN, out, HIDDEN,
        2*HIDDEN, b2, x, mod);
}

// round 5
// speedup vs baseline: 1.4504x; 1.4504x over previous
#include <cuda_runtime.h>
#include <cuda_bf16.h>
#include <math.h>
#include <stdint.h>

#define HIDDEN   1024
#define HEADS    16
#define HEAD_DIM 64
#define MLPH     4096
#define BB       2
#define LL       2048
#define NTOK     (BB*LL)          // 4096
#define W1N      (3*HIDDEN+MLPH)  // 7168

// ---------------- scratch (static device globals; no runtime alloc) ------------
__device__ float g_mod[BB*3*HIDDEN];        // shift|scale|gate per batch
__device__ float g_xmod[NTOK*HIDDEN];       // modulated LN output
__device__ float g_h[(size_t)NTOK*W1N];     // qkv(3072) | mlp(4096)
__device__ float g_y[(size_t)NTOK*2*HIDDEN];// attn(1024) | tanh-mlp(1024)

// =================== mma.sync TF32 GEMM =========================================
// C[M,N] = epilogue(A[M,K] @ B[K,N] + bias)
// CTA tile 128x128x32, 8 warps (2x4), warp tile 64x32.
// MODE 0: +bias   MODE 1: tanh(+bias)   MODE 2: x + gate * (+bias)
static constexpr int APITCH = 36;    // floats; (4g+t) conflict-free frag loads
static constexpr int BPITCH = 136;   // floats; (8t+g) conflict-free frag loads
static constexpr int OFF_A0 = 0;
static constexpr int OFF_A1 = 128*APITCH*4;            // 18432
static constexpr int OFF_B0 = OFF_A1*2;                // 36864
static constexpr int OFF_B1 = OFF_B0 + 32*BPITCH*4;    // 54272
static constexpr uint32_t GEMM_SMEM = OFF_B1 + 32*BPITCH*4;  // 71680

__device__ __forceinline__ uint32_t cvt_tf32(float x) {
    uint32_t r;
    asm("cvt.rna.tf32.f32 %0, %1;" : "=r"(r) : "f"(x));
    return r;
}
__device__ __forceinline__ void mma_tf32(float* c, const uint32_t* a, const uint32_t* b) {
    asm volatile(
        "mma.sync.aligned.m16n8k8.row.col.f32.tf32.tf32.f32 "
        "{%0,%1,%2,%3}, {%4,%5,%6,%7}, {%8,%9}, {%0,%1,%2,%3};"
        : "+f"(c[0]), "+f"(c[1]), "+f"(c[2]), "+f"(c[3])
        : "r"(a[0]), "r"(a[1]), "r"(a[2]), "r"(a[3]), "r"(b[0]), "r"(b[1]));
}

template<int MODE>
__global__ void __launch_bounds__(256) mma_gemm(
        const float* __restrict__ A, int lda,
        const float* __restrict__ B, int ldb,
        float* __restrict__ C, int ldc, int K,
        const float* __restrict__ bias,
        const float* __restrict__ xres,
        const float* __restrict__ mod) {
    extern __shared__ char smc[];
    uint32_t* const smu = (uint32_t*)smc;

    const int tid  = threadIdx.x;
    const int warp = tid >> 5;
    const int lane = tid & 31;
    const int g = lane >> 2;       // group of 4
    const int t = lane & 3;        // thread in group
    const int wm = (warp >> 2) * 64;   // warp m offset in CTA tile
    const int wn = (warp & 3) * 32;    // warp n offset
    const int bm = blockIdx.y << 7;
    const int bn = blockIdx.x << 7;

    // global load indices (128x32 A tile, 32x128 B tile, float4)
    const int a_row = tid >> 3, a_kq = (tid & 7) << 2;      // +32 rows per step
    const int b_row = tid >> 6, b_nq = (tid & 63) << 1;     // careful: set below

    float acc[4][4][4];
    #pragma unroll
    for (int i = 0; i < 4; i++)
        #pragma unroll
        for (int j = 0; j < 4; j++)
            #pragma unroll
            for (int e = 0; e < 4; e++) acc[i][j][e] = 0.0f;

    const int NT = K >> 5;
    float4 asg[4], bsg[4];

    // ---- prologue: tile 0 -> regs -> cvt -> SMEM buf0 ----
    {
        const float* Ag = A + (size_t)bm * lda;
        #pragma unroll
        for (int i = 0; i < 4; i++)
            asg[i] = *(const float4*)(Ag + (size_t)(a_row + 32*i) * lda + a_kq);
        const float* Bg = B + bn;
        #pragma unroll
        for (int i = 0; i < 4; i++) {
            int idx = (i << 8) + tid;           // 0..1023
            int r = idx >> 5, nq = (idx & 31) << 2;
            bsg[i] = *(const float4*)(Bg + (size_t)r * ldb + nq);
        }
        #pragma unroll
        for (int i = 0; i < 4; i++) {
            uint32_t* p = smu + (OFF_A0 >> 2) + (a_row + 32*i) * APITCH + a_kq;
            p[0]=cvt_tf32(asg[i].x); p[1]=cvt_tf32(asg[i].y);
            p[2]=cvt_tf32(asg[i].z); p[3]=cvt_tf32(asg[i].w);
        }
        #pragma unroll
        for (int i = 0; i < 4; i++) {
            int idx = (i << 8) + tid;
            int r = idx >> 5, nq = (idx & 31) << 2;
            uint32_t* p = smu + (OFF_B0 >> 2) + r * BPITCH + nq;
            p[0]=cvt_tf32(bsg[i].x); p[1]=cvt_tf32(bsg[i].y);
            p[2]=cvt_tf32(bsg[i].z); p[3]=cvt_tf32(bsg[i].w);
        }
    }
    __syncthreads();

    for (int kt = 0; kt < NT; kt++) {
        const int cur = kt & 1;
        // issue LDG for next tile early (latency overlap with MMA)
        if (kt + 1 < NT) {
            const int k0 = (kt + 1) << 5;
            const float* Ag = A + (size_t)bm * lda + k0;
            #pragma unroll
            for (int i = 0; i < 4; i++)
                asg[i] = *(const float4*)(Ag + (size_t)(a_row + 32*i) * lda + a_kq);
            const float* Bg = B + (size_t)k0 * ldb + bn;
            #pragma unroll
            for (int i = 0; i < 4; i++) {
                int idx = (i << 8) + tid;
                int r = idx >> 5, nq = (idx & 31) << 2;
                bsg[i] = *(const float4*)(Bg + (size_t)r * ldb + nq);
            }
        }

        const uint32_t* sA = smu + ((cur ? OFF_A1 : OFF_A0) >> 2);
        const uint32_t* sB = smu + ((cur ? OFF_B1 : OFF_B0) >> 2);
        #pragma unroll
        for (int kk = 0; kk < 4; kk++) {
            uint32_t af[4][4], bf[4][2];
            const int c0 = (kk << 3) + t;
            #pragma unroll
            for (int mt = 0; mt < 4; mt++) {
                const uint32_t* p = sA + (wm + (mt << 4) + g) * APITCH + c0;
                af[mt][0] = p[0];
                af[mt][1] = p[8 * APITCH];
                af[mt][2] = p[4];
                af[mt][3] = p[8 * APITCH + 4];
            }
            #pragma unroll
            for (int nt = 0; nt < 4; nt++) {
                const uint32_t* p = sB + c0 * BPITCH + wn + (nt << 3) + g;
                bf[nt][0] = p[0];
                bf[nt][1] = p[4 * BPITCH];
            }
            #pragma unroll
            for (int mt = 0; mt < 4; mt++)
                #pragma unroll
                for (int nt = 0; nt < 4; nt++)
                    mma_tf32(acc[mt][nt], af[mt], bf[nt]);
        }

        if (kt + 1 < NT) {
            const int nxt = cur ^ 1;
            #pragma unroll
            for (int i = 0; i < 4; i++) {
                uint32_t* p = smu + ((nxt ? OFF_A1 : OFF_A0) >> 2)
                            + (a_row + 32*i) * APITCH + a_kq;
                p[0]=cvt_tf32(asg[i].x); p[1]=cvt_tf32(asg[i].y);
                p[2]=cvt_tf32(asg[i].z); p[3]=cvt_tf32(asg[i].w);
            }
            #pragma unroll
            for (int i = 0; i < 4; i++) {
                int idx = (i << 8) + tid;
                int r = idx >> 5, nq = (idx & 31) << 2;
                uint32_t* p = smu + ((nxt ? OFF_B1 : OFF_B0) >> 2) + r * BPITCH + nq;
                p[0]=cvt_tf32(bsg[i].x); p[1]=cvt_tf32(bsg[i].y);
                p[2]=cvt_tf32(bsg[i].z); p[3]=cvt_tf32(bsg[i].w);
            }
        }
        __syncthreads();
    }

    // ---- epilogue ----
    #pragma unroll
    for (int nt = 0; nt < 4; nt++) {
        const int col = bn + wn + (nt << 3) + (t << 1);
        const float2 bi = *(const float2*)(bias + col);
        #pragma unroll
        for (int mt = 0; mt < 4; mt++) {
            const int r0 = bm + wm + (mt << 4) + g;
            float2 v0, v1;
            v0.x = acc[mt][nt][0] + bi.x;  v0.y = acc[mt][nt][1] + bi.y;
            v1.x = acc[mt][nt][2] + bi.x;  v1.y = acc[mt][nt][3] + bi.y;
            if (MODE == 1) {
                v0.x = tanhf(v0.x); v0.y = tanhf(v0.y);
                v1.x = tanhf(v1.x); v1.y = tanhf(v1.y);
            } else if (MODE == 2) {
                const int b0 = r0 >> 11;               // rows r0 and r0+8 same batch
                const float2 g2 = *(const float2*)(mod + b0*3*HIDDEN + 2*HIDDEN + col);
                const float2 x0 = *(const float2*)(xres + (size_t)r0*HIDDEN + col);
                const float2 x1 = *(const float2*)(xres + (size_t)(r0+8)*HIDDEN + col);
                v0.x = fmaf(g2.x, v0.x, x0.x); v0.y = fmaf(g2.y, v0.y, x0.y);
                v1.x = fmaf(g2.x, v1.x, x1.x); v1.y = fmaf(g2.y, v1.y, x1.y);
            }
            *(float2*)(C + (size_t)r0 * ldc + col)       = v0;
            *(float2*)(C + (size_t)(r0 + 8) * ldc + col) = v1;
        }
    }
}

// ---------------- kernel 1: mod = silu(vec) @ w_mod + b_mod --------------------
__global__ void mod_kernel(const float* __restrict__ vec,
                           const float* __restrict__ w_mod,
                           const float* __restrict__ b_mod,
                           float* __restrict__ mod) {
    __shared__ float sv[HIDDEN];
    int b = blockIdx.y;
    int n = blockIdx.x * 128 + threadIdx.x;
    for (int i = threadIdx.x; i < HIDDEN; i += 128) {
        float v = vec[b*HIDDEN + i];
        sv[i] = v / (1.0f + expf(-v));
    }
    __syncthreads();
    float acc = b_mod[n];
    #pragma unroll 8
    for (int k = 0; k < HIDDEN; k++)
        acc = fmaf(sv[k], w_mod[(size_t)k*3*HIDDEN + n], acc);
    mod[b*3*HIDDEN + n] = acc;
}

// ---------------- kernel 2: layernorm + modulate -------------------------------
__global__ void __launch_bounds__(256) ln_mod_kernel(const float* __restrict__ x,
                                                     const float* __restrict__ mod,
                                                     float* __restrict__ xmod) {
    __shared__ float sbuf[8];
    __shared__ float s_mean, s_rstd;
    int token = blockIdx.x;
    int b = token >> 11;
    int tid = threadIdx.x;
    const float4 xv = ((const float4*)(x + (size_t)token*HIDDEN))[tid];

    float s = xv.x + xv.y + xv.z + xv.w;
    #pragma unroll
    for (int o = 16; o > 0; o >>= 1) s += __shfl_xor_sync(0xffffffffu, s, o);
    if ((tid & 31) == 0) sbuf[tid >> 5] = s;
    __syncthreads();
    if (tid == 0) {
        float tq = 0;
        #pragma unroll
        for (int i = 0; i < 8; i++) tq += sbuf[i];
        s_mean = tq * (1.0f / HIDDEN);
    }
    __syncthreads();
    float m = s_mean;
    float dx = xv.x - m, dy = xv.y - m, dz = xv.z - m, dw = xv.w - m;
    float ss = dx*dx + dy*dy + dz*dz + dw*dw;
    #pragma unroll
    for (int o = 16; o > 0; o >>= 1) ss += __shfl_xor_sync(0xffffffffu, ss, o);
    __syncthreads();
    if ((tid & 31) == 0) sbuf[tid >> 5] = ss;
    __syncthreads();
    if (tid == 0) {
        float tq = 0;
        #pragma unroll
        for (int i = 0; i < 8; i++) tq += sbuf[i];
        s_rstd = rsqrtf(tq * (1.0f / HIDDEN) + 1e-6f);
    }
    __syncthreads();
    float r = s_rstd;
    int c = tid * 4;
    const float4 sh = *(const float4*)(mod + b*3*HIDDEN + c);
    const float4 sc = *(const float4*)(mod + b*3*HIDDEN + HIDDEN + c);
    float4 o4;
    o4.x = fmaf(1.0f + sc.x, dx*r, sh.x);
    o4.y = fmaf(1.0f + sc.y, dy*r, sh.y);
    o4.z = fmaf(1.0f + sc.z, dz*r, sh.z);
    o4.w = fmaf(1.0f + sc.w, dw*r, sh.w);
    ((float4*)(xmod + (size_t)token*HIDDEN))[tid] = o4;
}

// ---------------- kernel 4: per-head RMSNorm + RoPE on q,k (in place) ----------
__global__ void __launch_bounds__(512) qk_norm_rope_kernel(
        float* __restrict__ h,
        const float* __restrict__ pe,
        const float* __restrict__ q_scale,
        const float* __restrict__ k_scale) {
    int token = blockIdx.x;
    int l = token & (LL - 1);
    int head = threadIdx.x >> 5;
    int lane = threadIdx.x & 31;

    float* qp = h + (size_t)token*W1N + head*HEAD_DIM;
    float* kp = qp + HIDDEN;

    const float4 p = *(const float4*)(pe + (size_t)l*128 + lane*4);
    float sx = q_scale[lane*2], sy = q_scale[lane*2+1];
    float kx = k_scale[lane*2], ky = k_scale[lane*2+1];

    {
        float2 q2 = *(float2*)(qp + lane*2);
        float ss = q2.x*q2.x + q2.y*q2.y;
        #pragma unroll
        for (int o = 16; o > 0; o >>= 1) ss += __shfl_xor_sync(0xffffffffu, ss, o);
        float rr = rsqrtf(ss * (1.0f/HEAD_DIM) + 1e-6f);
        float t0 = q2.x * rr * sx, t1 = q2.y * rr * sy;
        float2 o2;
        o2.x = p.x*t0 + p.y*t1;
        o2.y = p.z*t0 + p.w*t1;
        *(float2*)(qp + lane*2) = o2;
    }
    {
        float2 k2 = *(float2*)(kp + lane*2);
        float ss = k2.x*k2.x + k2.y*k2.y;
        #pragma unroll
        for (int o = 16; o > 0; o >>= 1) ss += __shfl_xor_sync(0xffffffffu, ss, o);
        float rr = rsqrtf(ss * (1.0f/HEAD_DIM) + 1e-6f);
        float t0 = k2.x * rr * kx, t1 = k2.y * rr * ky;
        float2 o2;
        o2.x = p.x*t0 + p.y*t1;
        o2.y = p.z*t0 + p.w*t1;
        *(float2*)(kp + lane*2) = o2;
    }
}

// ---------------- kernel 5: flash attention (fp32) -----------------------------
__global__ void __launch_bounds__(256) attn_kernel(const float* __restrict__ h,
                                                   float* __restrict__ y) {
    __shared__ float Qs[64][68];
    __shared__ float Ks[32][68];
    __shared__ float Vs[32][68];
    __shared__ float Ss[64][33];
    __shared__ float m_sm[64], l_sm[64], f_sm[64];

    const int tid = threadIdx.x;
    const int bh = blockIdx.y;
    const int b = bh >> 4, hd = bh & 15;
    const int q0 = blockIdx.x << 6;
    const float* base = h + (size_t)b*LL*W1N + hd*HEAD_DIM;

    for (int i = tid; i < 1024; i += 256) {
        int r = i >> 4, c = (i & 15) << 2;
        *(float4*)&Qs[r][c] = *(const float4*)(base + (size_t)(q0 + r)*W1N + c);
    }
    if (tid < 64) { m_sm[tid] = -1e30f; l_sm[tid] = 0.0f; }

    float o[16];
    #pragma unroll
    for (int i = 0; i < 16; i++) o[i] = 0.0f;
    const int ro = tid >> 2, dg = (tid & 3) << 4;
    const int r2 = tid >> 3, kl = tid & 7;
    __syncthreads();

    for (int kt = 0; kt < LL/32; kt++) {
        int krow0 = kt << 5;
        for (int i = tid; i < 512; i += 256) {
            int r = i >> 4, c = (i & 15) << 2;
            const float* kp = base + HIDDEN + (size_t)(krow0 + r)*W1N + c;
            *(float4*)&Ks[r][c] = *(const float4*)kp;
            *(float4*)&Vs[r][c] = *(const float4*)(kp + HIDDEN);
        }
        __syncthreads();

        float a0[4] = {0,0,0,0}, a1[4] = {0,0,0,0};
        #pragma unroll
        for (int d = 0; d < 64; d += 4) {
            float4 qa = *(float4*)&Qs[r2][d];
            float4 qb = *(float4*)&Qs[r2+32][d];
            #pragma unroll
            for (int j = 0; j < 4; j++) {
                float4 k4 = *(float4*)&Ks[kl + (j<<3)][d];
                a0[j] += qa.x*k4.x + qa.y*k4.y + qa.z*k4.z + qa.w*k4.w;
                a1[j] += qb.x*k4.x + qb.y*k4.y + qb.z*k4.z + qb.w*k4.w;
            }
        }
        #pragma unroll
        for (int j = 0; j < 4; j++) {
            Ss[r2][kl + (j<<3)]    = a0[j] * 0.125f;
            Ss[r2+32][kl + (j<<3)] = a1[j] * 0.125f;
        }
        __syncthreads();

        if (tid < 64) {
            float mo = m_sm[tid];
            float mx = mo;
            #pragma unroll
            for (int k = 0; k < 32; k++) mx = fmaxf(mx, Ss[tid][k]);
            float f = __expf(mo - mx);
            float s = 0.0f;
            #pragma unroll
            for (int k = 0; k < 32; k++) {
                float pv = __expf(Ss[tid][k] - mx);
                Ss[tid][k] = pv;
                s += pv;
            }
            m_sm[tid] = mx;
            l_sm[tid] = l_sm[tid]*f + s;
            f_sm[tid] = f;
        }
        __syncthreads();

        float f = f_sm[ro];
        #pragma unroll
        for (int i = 0; i < 16; i++) o[i] *= f;
        #pragma unroll
        for (int k = 0; k < 32; k++) {
            float pv = Ss[ro][k];
            float4 v0 = *(float4*)&Vs[k][dg];
            float4 v1 = *(float4*)&Vs[k][dg+4];
            float4 v2 = *(float4*)&Vs[k][dg+8];
            float4 v3 = *(float4*)&Vs[k][dg+12];
            o[0]  = fmaf(pv, v0.x, o[0]);  o[1]  = fmaf(pv, v0.y, o[1]);
            o[2]  = fmaf(pv, v0.z, o[2]);  o[3]  = fmaf(pv, v0.w, o[3]);
            o[4]  = fmaf(pv, v1.x, o[4]);  o[5]  = fmaf(pv, v1.y, o[5]);
            o[6]  = fmaf(pv, v1.z, o[6]);  o[7]  = fmaf(pv, v1.w, o[7]);
            o[8]  = fmaf(pv, v2.x, o[8]);  o[9]  = fmaf(pv, v2.y, o[9]);
            o[10] = fmaf(pv, v2.z, o[10]); o[11] = fmaf(pv, v2.w, o[11]);
            o[12] = fmaf(pv, v3.x, o[12]); o[13] = fmaf(pv, v3.y, o[13]);
            o[14] = fmaf(pv, v3.z, o[14]); o[15] = fmaf(pv, v3.w, o[15]);
        }
        __syncthreads();
    }

    float inv = 1.0f / l_sm[ro];
    float* yp = y + (size_t)(b*LL + q0 + ro)*(2*HIDDEN) + hd*HEAD_DIM + dg;
    float4 w0, w1, w2, w3;
    w0.x=o[0]*inv;  w0.y=o[1]*inv;  w0.z=o[2]*inv;  w0.w=o[3]*inv;
    w1.x=o[4]*inv;  w1.y=o[5]*inv;  w1.z=o[6]*inv;  w1.w=o[7]*inv;
    w2.x=o[8]*inv;  w2.y=o[9]*inv;  w2.z=o[10]*inv; w2.w=o[11]*inv;
    w3.x=o[12]*inv; w3.y=o[13]*inv; w3.z=o[14]*inv; w3.w=o[15]*inv;
    *(float4*)(yp)    = w0;
    *(float4*)(yp+4)  = w1;
    *(float4*)(yp+8)  = w2;
    *(float4*)(yp+12) = w3;
}

// ---------------- launch --------------------------------------------------------
extern "C" void kernel_launch(void* const* d_in, const int* in_sizes, int n_in,
                              void* d_out, int out_size) {
    const float* x       = (const float*)d_in[0];
    const float* vec     = (const float*)d_in[1];
    const float* pe      = (const float*)d_in[2];
    const float* w_mod   = (const float*)d_in[3];
    const float* b_mod   = (const float*)d_in[4];
    const float* w1      = (const float*)d_in[5];
    const float* b1      = (const float*)d_in[6];
    const float* w_mlp   = (const float*)d_in[7];
    const float* b_mlp   = (const float*)d_in[8];
    const float* w2      = (const float*)d_in[9];
    const float* b2      = (const float*)d_in[10];
    const float* q_scale = (const float*)d_in[11];
    const float* k_scale = (const float*)d_in[12];
    float* out = (float*)d_out;

    float *mod, *xmod, *h, *y;
    cudaGetSymbolAddress((void**)&mod,  g_mod);
    cudaGetSymbolAddress((void**)&xmod, g_xmod);
    cudaGetSymbolAddress((void**)&h,    g_h);
    cudaGetSymbolAddress((void**)&y,    g_y);

    cudaFuncSetAttribute(mma_gemm<0>, cudaFuncAttributeMaxDynamicSharedMemorySize, GEMM_SMEM);
    cudaFuncSetAttribute(mma_gemm<1>, cudaFuncAttributeMaxDynamicSharedMemorySize, GEMM_SMEM);
    cudaFuncSetAttribute(mma_gemm<2>, cudaFuncAttributeMaxDynamicSharedMemorySize, GEMM_SMEM);

    // 1. modulation vector
    mod_kernel<<<dim3(3*HIDDEN/128, BB), 128>>>(vec, w_mod, b_mod, mod);
    // 2. layernorm + modulate
    ln_mod_kernel<<<NTOK, 256>>>(x, mod, xmod);
    // 3. h = x_mod @ w1 + b1   (4096 x 7168, K=1024)  [mma.sync tf32]
    mma_gemm<0><<<dim3(W1N/128, NTOK/128), 256, GEMM_SMEM>>>(
        xmod, HIDDEN, w1, W1N, h, W1N, HIDDEN, b1, nullptr, nullptr);
    // 4. q,k rmsnorm + rope in place
    qk_norm_rope_kernel<<<NTOK, 512>>>(h, pe, q_scale, k_scale);
    // 5. attention -> y[:, :1024]
    attn_kernel<<<dim3(LL/64, BB*HEADS), 256>>>(h, y);
    // 6. y[:, 1024:] = tanh(mlp @ w_mlp + b_mlp)   (4096 x 1024, K=4096)
    mma_gemm<1><<<dim3(HIDDEN/128, NTOK/128), 256, GEMM_SMEM>>>(
        h + 3*HIDDEN, W1N, w_mlp, HIDDEN, y + HIDDEN, 2*HIDDEN,
        MLPH, b_mlp, nullptr, nullptr);
    // 7. out = x + gate * (y @ w2 + b2)   (4096 x 1024, K=2048)
    mma_gemm<2><<<dim3(HIDDEN/128, NTOK/128), 256, GEMM_SMEM>>>(
        y, 2*HIDDEN, w2, HIDDEN, out, HIDDEN,
        2*HIDDEN, b2, x, mod);
}

// round 6
// speedup vs baseline: 4.2232x; 2.9118x over previous
#include <cuda_runtime.h>
#include <cuda_bf16.h>
#include <math.h>
#include <stdint.h>

#define HIDDEN   1024
#define HEADS    16
#define HEAD_DIM 64
#define MLPH     4096
#define BB       2
#define LL       2048
#define NTOK     (BB*LL)          // 4096
#define W1N      (3*HIDDEN+MLPH)  // 7168

// ---------------- scratch (static device globals; no runtime alloc) ------------
__device__ float g_mod[BB*3*HIDDEN];
__device__ float g_xmod[NTOK*HIDDEN];
__device__ float g_h[(size_t)NTOK*W1N];      // qkv(3072) | mlp(4096)
__device__ float g_y[(size_t)NTOK*2*HIDDEN]; // attn(1024) | tanh-mlp(1024)

// =================== helpers ====================================================
__device__ __forceinline__ uint32_t smem_u32(const void* p) {
    uint32_t a;
    asm("{ .reg .u64 t; cvta.to.shared.u64 t, %1; cvt.u32.u64 %0, t; }"
        : "=r"(a) : "l"(p));
    return a;
}
__device__ __forceinline__ uint32_t cvt_tf32(float x) {
    uint32_t r;
    asm("cvt.rna.tf32.f32 %0, %1;" : "=r"(r) : "f"(x));
    return r;
}
__device__ __forceinline__ uint32_t pack_bf16(float lo, float hi) {
    uint32_t r;
    asm("cvt.rn.bf16x2.f32 %0, %1, %2;" : "=r"(r) : "f"(hi), "f"(lo));
    return r;
}
__device__ __forceinline__ void mma_tf32(float* c, const uint32_t* a, const uint32_t* b) {
    asm volatile(
        "mma.sync.aligned.m16n8k8.row.col.f32.tf32.tf32.f32 "
        "{%0,%1,%2,%3}, {%4,%5,%6,%7}, {%8,%9}, {%0,%1,%2,%3};"
        : "+f"(c[0]), "+f"(c[1]), "+f"(c[2]), "+f"(c[3])
        : "r"(a[0]), "r"(a[1]), "r"(a[2]), "r"(a[3]), "r"(b[0]), "r"(b[1]));
}
__device__ __forceinline__ void mma_bf16(float* c, const uint32_t* a, const uint32_t* b) {
    asm volatile(
        "mma.sync.aligned.m16n8k16.row.col.f32.bf16.bf16.f32 "
        "{%0,%1,%2,%3}, {%4,%5,%6,%7}, {%8,%9}, {%0,%1,%2,%3};"
        : "+f"(c[0]), "+f"(c[1]), "+f"(c[2]), "+f"(c[3])
        : "r"(a[0]), "r"(a[1]), "r"(a[2]), "r"(a[3]), "r"(b[0]), "r"(b[1]));
}
__device__ __forceinline__ void cp16(uint32_t dst, const void* src) {
    asm volatile("cp.async.cg.shared.global [%0], [%1], 16;" :: "r"(dst), "l"(src));
}
__device__ __forceinline__ void cp_commit() {
    asm volatile("cp.async.commit_group;" ::: "memory");
}
template<int N>
__device__ __forceinline__ void cp_wait() {
    asm volatile("cp.async.wait_group %0;" :: "n"(N) : "memory");
}

// =================== GEMM v2: cp.async 3-stage, mma.sync tf32 ==================
// C[M,N] = epilogue(A[M,K] @ B[K,N] + bias)
// CTA tile 128x128x32, 8 warps (2x4), warp tile 64x32.
// Stages hold raw f32; cvt.rna applied at fragment build.
static constexpr int APITCH = 36;                     // floats
static constexpr int BPITCH = 136;                    // floats
static constexpr int STAGE_F = 128*APITCH + 32*BPITCH;// 8960 floats = 35840 B
static constexpr uint32_t GEMM_SMEM = 3 * STAGE_F * 4;// 107520 B

__device__ __forceinline__ void gemm_issue(
        const float* __restrict__ A, int lda,
        const float* __restrict__ B, int ldb,
        int bm, int bn, int kt, int slot, uint32_t sbase, int tid) {
    const float* Ag = A + (size_t)bm * lda + (kt << 5);
    uint32_t dA = sbase + slot * (STAGE_F * 4);
    #pragma unroll
    for (int i = 0; i < 4; i++) {
        int idx = (i << 8) + tid;
        int r = idx >> 3, kq = (idx & 7) << 2;
        cp16(dA + (r * APITCH + kq) * 4, Ag + (size_t)r * lda + kq);
    }
    const float* Bg = B + (size_t)(kt << 5) * ldb + bn;
    uint32_t dB = dA + 128 * APITCH * 4;
    #pragma unroll
    for (int i = 0; i < 4; i++) {
        int idx = (i << 8) + tid;
        int r = idx >> 5, nq = (idx & 31) << 2;
        cp16(dB + (r * BPITCH + nq) * 4, Bg + (size_t)r * ldb + nq);
    }
    cp_commit();
}

template<int MODE>
__global__ void __launch_bounds__(256) mma_gemm(
        const float* __restrict__ A, int lda,
        const float* __restrict__ B, int ldb,
        float* __restrict__ C, int ldc, int K,
        const float* __restrict__ bias,
        const float* __restrict__ xres,
        const float* __restrict__ mod) {
    extern __shared__ char smc[];
    float* const smf = (float*)smc;
    const uint32_t sbase = smem_u32(smc);

    const int tid  = threadIdx.x;
    const int warp = tid >> 5;
    const int lane = tid & 31;
    const int g = lane >> 2, t = lane & 3;
    const int wm = (warp >> 2) * 64;
    const int wn = (warp & 3) * 32;
    const int bm = blockIdx.y << 7;
    const int bn = blockIdx.x << 7;

    float acc[4][4][4];
    #pragma unroll
    for (int i = 0; i < 4; i++)
        #pragma unroll
        for (int j = 0; j < 4; j++)
            #pragma unroll
            for (int e = 0; e < 4; e++) acc[i][j][e] = 0.0f;

    const int NT = K >> 5;
    gemm_issue(A, lda, B, ldb, bm, bn, 0, 0, sbase, tid);
    gemm_issue(A, lda, B, ldb, bm, bn, 1, 1, sbase, tid);

    for (int kt = 0; kt < NT; kt++) {
        if (kt + 1 < NT) cp_wait<1>(); else cp_wait<0>();
        __syncthreads();
        if (kt + 2 < NT) {
            int s3 = (kt + 2) % 3;
            gemm_issue(A, lda, B, ldb, bm, bn, kt + 2, s3, sbase, tid);
        }
        const float* sA = smf + (kt % 3) * STAGE_F;
        const float* sB = sA + 128 * APITCH;
        #pragma unroll
        for (int kk = 0; kk < 4; kk++) {
            const int c0 = (kk << 3) + t;
            uint32_t af[4][4], bf[4][2];
            #pragma unroll
            for (int mt = 0; mt < 4; mt++) {
                const float* p = sA + (wm + (mt << 4) + g) * APITCH + c0;
                af[mt][0] = cvt_tf32(p[0]);
                af[mt][1] = cvt_tf32(p[8 * APITCH]);
                af[mt][2] = cvt_tf32(p[4]);
                af[mt][3] = cvt_tf32(p[8 * APITCH + 4]);
            }
            #pragma unroll
            for (int nt = 0; nt < 4; nt++) {
                const float* p = sB + c0 * BPITCH + wn + (nt << 3) + g;
                bf[nt][0] = cvt_tf32(p[0]);
                bf[nt][1] = cvt_tf32(p[4 * BPITCH]);
            }
            #pragma unroll
            for (int mt = 0; mt < 4; mt++)
                #pragma unroll
                for (int nt = 0; nt < 4; nt++)
                    mma_tf32(acc[mt][nt], af[mt], bf[nt]);
        }
    }

    // ---- epilogue ----
    #pragma unroll
    for (int nt = 0; nt < 4; nt++) {
        const int col = bn + wn + (nt << 3) + (t << 1);
        const float2 bi = *(const float2*)(bias + col);
        #pragma unroll
        for (int mt = 0; mt < 4; mt++) {
            const int r0 = bm + wm + (mt << 4) + g;
            float2 v0, v1;
            v0.x = acc[mt][nt][0] + bi.x;  v0.y = acc[mt][nt][1] + bi.y;
            v1.x = acc[mt][nt][2] + bi.x;  v1.y = acc[mt][nt][3] + bi.y;
            if (MODE == 1) {
                v0.x = tanhf(v0.x); v0.y = tanhf(v0.y);
                v1.x = tanhf(v1.x); v1.y = tanhf(v1.y);
            } else if (MODE == 2) {
                const int b0 = r0 >> 11;
                const float2 g2 = *(const float2*)(mod + b0*3*HIDDEN + 2*HIDDEN + col);
                const float2 x0 = *(const float2*)(xres + (size_t)r0*HIDDEN + col);
                const float2 x1 = *(const float2*)(xres + (size_t)(r0+8)*HIDDEN + col);
                v0.x = fmaf(g2.x, v0.x, x0.x); v0.y = fmaf(g2.y, v0.y, x0.y);
                v1.x = fmaf(g2.x, v1.x, x1.x); v1.y = fmaf(g2.y, v1.y, x1.y);
            }
            *(float2*)(C + (size_t)r0 * ldc + col)       = v0;
            *(float2*)(C + (size_t)(r0 + 8) * ldc + col) = v1;
        }
    }
}

// =================== tensor-core flash attention ================================
// CTA: 128 q-rows x d=64 for one (b,h). 8 warps, 16 rows each.
// QK^T in tf32 mma, softmax in registers, P@V in bf16 mma.
// SMEM: K tiles [key][d] f32 pitch 68, double buffered; V same. 69632 B.
static constexpr int KV_PITCH = 68;                    // floats
static constexpr int KV_TILE_F = 64 * KV_PITCH;        // 4352 floats = 17408 B
static constexpr uint32_t ATTN_SMEM = 4 * KV_TILE_F * 4; // 69632 B

__device__ __forceinline__ void attn_issue_kv(
        const float* __restrict__ kbase, const float* __restrict__ vbase,
        int kt, int slot, uint32_t sbase, int tid) {
    const int krow0 = kt << 6;
    uint32_t dK = sbase + slot * (KV_TILE_F * 4);
    uint32_t dV = sbase + (2 + slot) * (KV_TILE_F * 4);
    #pragma unroll
    for (int i = 0; i < 4; i++) {
        int idx = (i << 8) + tid;
        int r = idx >> 4, cq = (idx & 15) << 2;
        const float* src = kbase + (size_t)(krow0 + r) * W1N + cq;
        cp16(dK + (r * KV_PITCH + cq) * 4, src);
        cp16(dV + (r * KV_PITCH + cq) * 4, src + HIDDEN);
    }
    cp_commit();
}

__global__ void __launch_bounds__(256) attn_tc(const float* __restrict__ h,
                                               float* __restrict__ y) {
    extern __shared__ char smc[];
    float* const smf = (float*)smc;
    const uint32_t sbase = smem_u32(smc);

    const int tid  = threadIdx.x;
    const int warp = tid >> 5;
    const int lane = tid & 31;
    const int g = lane >> 2, t = lane & 3;
    const int bh = blockIdx.y;
    const int b = bh >> 4, hd = bh & 15;
    const int q0 = blockIdx.x << 7;

    const float* qbase = h + (size_t)b * LL * W1N + hd * HEAD_DIM;
    const float* kbase = qbase + HIDDEN;
    const float* vbase = qbase + 2 * HIDDEN;

    // ---- stage Q tile (128 x 64) into smem, build per-warp a-frags ----
    #pragma unroll
    for (int i = 0; i < 8; i++) {
        int idx = (i << 8) + tid;
        int r = idx >> 4, cq = (idx & 15) << 2;
        *(float4*)(smf + r * KV_PITCH + cq) =
            *(const float4*)(qbase + (size_t)(q0 + r) * W1N + cq);
    }
    __syncthreads();
    uint32_t qa[8][4];
    {
        const int r0 = warp << 4;
        #pragma unroll
        for (int kk = 0; kk < 8; kk++) {
            const float* p = smf + (r0 + g) * KV_PITCH + (kk << 3) + t;
            qa[kk][0] = cvt_tf32(0.125f * p[0]);
            qa[kk][1] = cvt_tf32(0.125f * p[8 * KV_PITCH]);
            qa[kk][2] = cvt_tf32(0.125f * p[4]);
            qa[kk][3] = cvt_tf32(0.125f * p[8 * KV_PITCH + 4]);
        }
    }
    __syncthreads();

    float o[8][4];
    #pragma unroll
    for (int dn = 0; dn < 8; dn++)
        #pragma unroll
        for (int e = 0; e < 4; e++) o[dn][e] = 0.0f;
    float m0 = -1e30f, m1 = -1e30f, l0 = 0.0f, l1 = 0.0f;

    attn_issue_kv(kbase, vbase, 0, 0, sbase, tid);

    const int NT = LL / 64;   // 32
    for (int kt = 0; kt < NT; kt++) {
        cp_wait<0>();
        __syncthreads();
        if (kt + 1 < NT)
            attn_issue_kv(kbase, vbase, kt + 1, (kt + 1) & 1, sbase, tid);

        const int slot = kt & 1;
        const float* sK = smf + slot * KV_TILE_F;
        const float* sV = smf + (2 + slot) * KV_TILE_F;

        // ---- S = Q @ K^T (tf32) ----
        float s[8][4];
        #pragma unroll
        for (int nt = 0; nt < 8; nt++)
            #pragma unroll
            for (int e = 0; e < 4; e++) s[nt][e] = 0.0f;
        #pragma unroll
        for (int kk = 0; kk < 8; kk++) {
            const int c0 = (kk << 3) + t;
            #pragma unroll
            for (int nt = 0; nt < 8; nt++) {
                uint32_t kb[2];
                const float* p = sK + ((nt << 3) + g) * KV_PITCH + c0;
                kb[0] = cvt_tf32(p[0]);
                kb[1] = cvt_tf32(p[4]);
                mma_tf32(s[nt], qa[kk], kb);
            }
        }

        // ---- online softmax (rows g and g+8) ----
        float mx0 = -1e30f, mx1 = -1e30f;
        #pragma unroll
        for (int nt = 0; nt < 8; nt++) {
            mx0 = fmaxf(mx0, fmaxf(s[nt][0], s[nt][1]));
            mx1 = fmaxf(mx1, fmaxf(s[nt][2], s[nt][3]));
        }
        mx0 = fmaxf(mx0, __shfl_xor_sync(0xffffffffu, mx0, 1));
        mx0 = fmaxf(mx0, __shfl_xor_sync(0xffffffffu, mx0, 2));
        mx1 = fmaxf(mx1, __shfl_xor_sync(0xffffffffu, mx1, 1));
        mx1 = fmaxf(mx1, __shfl_xor_sync(0xffffffffu, mx1, 2));
        const float M0 = fmaxf(m0, mx0), M1 = fmaxf(m1, mx1);
        const float f0 = __expf(m0 - M0), f1 = __expf(m1 - M1);
        m0 = M0; m1 = M1;

        float sum0 = 0.0f, sum1 = 0.0f;
        #pragma unroll
        for (int nt = 0; nt < 8; nt++) {
            s[nt][0] = __expf(s[nt][0] - M0);
            s[nt][1] = __expf(s[nt][1] - M0);
            s[nt][2] = __expf(s[nt][2] - M1);
            s[nt][3] = __expf(s[nt][3] - M1);
            sum0 += s[nt][0] + s[nt][1];
            sum1 += s[nt][2] + s[nt][3];
        }
        sum0 += __shfl_xor_sync(0xffffffffu, sum0, 1);
        sum0 += __shfl_xor_sync(0xffffffffu, sum0, 2);
        sum1 += __shfl_xor_sync(0xffffffffu, sum1, 1);
        sum1 += __shfl_xor_sync(0xffffffffu, sum1, 2);
        l0 = l0 * f0 + sum0;
        l1 = l1 * f1 + sum1;

        #pragma unroll
        for (int dn = 0; dn < 8; dn++) {
            o[dn][0] *= f0; o[dn][1] *= f0;
            o[dn][2] *= f1; o[dn][3] *= f1;
        }

        // ---- P (bf16 a-frags) ----
        uint32_t pa[4][4];
        #pragma unroll
        for (int kc = 0; kc < 4; kc++) {
            pa[kc][0] = pack_bf16(s[2*kc][0],   s[2*kc][1]);
            pa[kc][1] = pack_bf16(s[2*kc][2],   s[2*kc][3]);
            pa[kc][2] = pack_bf16(s[2*kc+1][0], s[2*kc+1][1]);
            pa[kc][3] = pack_bf16(s[2*kc+1][2], s[2*kc+1][3]);
        }

        // ---- O += P @ V (bf16) ----
        #pragma unroll
        for (int kc = 0; kc < 4; kc++) {
            const float* vp = sV + ((kc << 4) + 2*t) * KV_PITCH + g;
            #pragma unroll
            for (int dn = 0; dn < 8; dn++) {
                const float* p = vp + (dn << 3);
                uint32_t vb[2];
                vb[0] = pack_bf16(p[0],            p[KV_PITCH]);
                vb[1] = pack_bf16(p[8*KV_PITCH],   p[9*KV_PITCH]);
                mma_bf16(o[dn], pa[kc], vb);
            }
        }
        __syncthreads();
    }

    // ---- write O / l ----
    const float il0 = 1.0f / l0, il1 = 1.0f / l1;
    const int row0 = b * LL + q0 + (warp << 4) + g;
    float* yp0 = y + (size_t)row0 * (2*HIDDEN) + hd * HEAD_DIM + (t << 1);
    float* yp1 = yp0 + (size_t)8 * (2*HIDDEN);
    #pragma unroll
    for (int dn = 0; dn < 8; dn++) {
        float2 v0, v1;
        v0.x = o[dn][0] * il0; v0.y = o[dn][1] * il0;
        v1.x = o[dn][2] * il1; v1.y = o[dn][3] * il1;
        *(float2*)(yp0 + (dn << 3)) = v0;
        *(float2*)(yp1 + (dn << 3)) = v1;
    }
}

// ---------------- kernel 1: mod = silu(vec) @ w_mod + b_mod --------------------
__global__ void mod_kernel(const float* __restrict__ vec,
                           const float* __restrict__ w_mod,
                           const float* __restrict__ b_mod,
                           float* __restrict__ mod) {
    __shared__ float sv[HIDDEN];
    int b = blockIdx.y;
    int n = blockIdx.x * 128 + threadIdx.x;
    for (int i = threadIdx.x; i < HIDDEN; i += 128) {
        float v = vec[b*HIDDEN + i];
        sv[i] = v / (1.0f + expf(-v));
    }
    __syncthreads();
    float acc = b_mod[n];
    #pragma unroll 8
    for (int k = 0; k < HIDDEN; k++)
        acc = fmaf(sv[k], w_mod[(size_t)k*3*HIDDEN + n], acc);
    mod[b*3*HIDDEN + n] = acc;
}

// ---------------- kernel 2: layernorm + modulate -------------------------------
__global__ void __launch_bounds__(256) ln_mod_kernel(const float* __restrict__ x,
                                                     const float* __restrict__ mod,
                                                     float* __restrict__ xmod) {
    __shared__ float sbuf[8];
    __shared__ float s_mean, s_rstd;
    int token = blockIdx.x;
    int b = token >> 11;
    int tid = threadIdx.x;
    const float4 xv = ((const float4*)(x + (size_t)token*HIDDEN))[tid];

    float s = xv.x + xv.y + xv.z + xv.w;
    #pragma unroll
    for (int o = 16; o > 0; o >>= 1) s += __shfl_xor_sync(0xffffffffu, s, o);
    if ((tid & 31) == 0) sbuf[tid >> 5] = s;
    __syncthreads();
    if (tid == 0) {
        float tq = 0;
        #pragma unroll
        for (int i = 0; i < 8; i++) tq += sbuf[i];
        s_mean = tq * (1.0f / HIDDEN);
    }
    __syncthreads();
    float m = s_mean;
    float dx = xv.x - m, dy = xv.y - m, dz = xv.z - m, dw = xv.w - m;
    float ss = dx*dx + dy*dy + dz*dz + dw*dw;
    #pragma unroll
    for (int o = 16; o > 0; o >>= 1) ss += __shfl_xor_sync(0xffffffffu, ss, o);
    __syncthreads();
    if ((tid & 31) == 0) sbuf[tid >> 5] = ss;
    __syncthreads();
    if (tid == 0) {
        float tq = 0;
        #pragma unroll
        for (int i = 0; i < 8; i++) tq += sbuf[i];
        s_rstd = rsqrtf(tq * (1.0f / HIDDEN) + 1e-6f);
    }
    __syncthreads();
    float r = s_rstd;
    int c = tid * 4;
    const float4 sh = *(const float4*)(mod + b*3*HIDDEN + c);
    const float4 sc = *(const float4*)(mod + b*3*HIDDEN + HIDDEN + c);
    float4 o4;
    o4.x = fmaf(1.0f + sc.x, dx*r, sh.x);
    o4.y = fmaf(1.0f + sc.y, dy*r, sh.y);
    o4.z = fmaf(1.0f + sc.z, dz*r, sh.z);
    o4.w = fmaf(1.0f + sc.w, dw*r, sh.w);
    ((float4*)(xmod + (size_t)token*HIDDEN))[tid] = o4;
}

// ---------------- kernel 4: per-head RMSNorm + RoPE on q,k (in place) ----------
__global__ void __launch_bounds__(512) qk_norm_rope_kernel(
        float* __restrict__ h,
        const float* __restrict__ pe,
        const float* __restrict__ q_scale,
        const float* __restrict__ k_scale) {
    int token = blockIdx.x;
    int l = token & (LL - 1);
    int head = threadIdx.x >> 5;
    int lane = threadIdx.x & 31;

    float* qp = h + (size_t)token*W1N + head*HEAD_DIM;
    float* kp = qp + HIDDEN;

    const float4 p = *(const float4*)(pe + (size_t)l*128 + lane*4);
    float sx = q_scale[lane*2], sy = q_scale[lane*2+1];
    float kx = k_scale[lane*2], ky = k_scale[lane*2+1];

    {
        float2 q2 = *(float2*)(qp + lane*2);
        float ss = q2.x*q2.x + q2.y*q2.y;
        #pragma unroll
        for (int o = 16; o > 0; o >>= 1) ss += __shfl_xor_sync(0xffffffffu, ss, o);
        float rr = rsqrtf(ss * (1.0f/HEAD_DIM) + 1e-6f);
        float t0 = q2.x * rr * sx, t1 = q2.y * rr * sy;
        float2 o2;
        o2.x = p.x*t0 + p.y*t1;
        o2.y = p.z*t0 + p.w*t1;
        *(float2*)(qp + lane*2) = o2;
    }
    {
        float2 k2 = *(float2*)(kp + lane*2);
        float ss = k2.x*k2.x + k2.y*k2.y;
        #pragma unroll
        for (int o = 16; o > 0; o >>= 1) ss += __shfl_xor_sync(0xffffffffu, ss, o);
        float rr = rsqrtf(ss * (1.0f/HEAD_DIM) + 1e-6f);
        float t0 = k2.x * rr * kx, t1 = k2.y * rr * ky;
        float2 o2;
        o2.x = p.x*t0 + p.y*t1;
        o2.y = p.z*t0 + p.w*t1;
        *(float2*)(kp + lane*2) = o2;
    }
}

// ---------------- launch --------------------------------------------------------
extern "C" void kernel_launch(void* const* d_in, const int* in_sizes, int n_in,
                              void* d_out, int out_size) {
    const float* x       = (const float*)d_in[0];
    const float* vec     = (const float*)d_in[1];
    const float* pe      = (const float*)d_in[2];
    const float* w_mod   = (const float*)d_in[3];
    const float* b_mod   = (const float*)d_in[4];
    const float* w1      = (const float*)d_in[5];
    const float* b1      = (const float*)d_in[6];
    const float* w_mlp   = (const float*)d_in[7];
    const float* b_mlp   = (const float*)d_in[8];
    const float* w2      = (const float*)d_in[9];
    const float* b2      = (const float*)d_in[10];
    const float* q_scale = (const float*)d_in[11];
    const float* k_scale = (const float*)d_in[12];
    float* out = (float*)d_out;

    float *mod, *xmod, *h, *y;
    cudaGetSymbolAddress((void**)&mod,  g_mod);
    cudaGetSymbolAddress((void**)&xmod, g_xmod);
    cudaGetSymbolAddress((void**)&h,    g_h);
    cudaGetSymbolAddress((void**)&y,    g_y);

    cudaFuncSetAttribute(mma_gemm<0>, cudaFuncAttributeMaxDynamicSharedMemorySize, GEMM_SMEM);
    cudaFuncSetAttribute(mma_gemm<1>, cudaFuncAttributeMaxDynamicSharedMemorySize, GEMM_SMEM);
    cudaFuncSetAttribute(mma_gemm<2>, cudaFuncAttributeMaxDynamicSharedMemorySize, GEMM_SMEM);
    cudaFuncSetAttribute(attn_tc,     cudaFuncAttributeMaxDynamicSharedMemorySize, ATTN_SMEM);

    // 1. modulation vector
    mod_kernel<<<dim3(3*HIDDEN/128, BB), 128>>>(vec, w_mod, b_mod, mod);
    // 2. layernorm + modulate
    ln_mod_kernel<<<NTOK, 256>>>(x, mod, xmod);
    // 3. h = x_mod @ w1 + b1   (4096 x 7168, K=1024)
    mma_gemm<0><<<dim3(W1N/128, NTOK/128), 256, GEMM_SMEM>>>(
        xmod, HIDDEN, w1, W1N, h, W1N, HIDDEN, b1, nullptr, nullptr);
    // 4. q,k rmsnorm + rope in place
    qk_norm_rope_kernel<<<NTOK, 512>>>(h, pe, q_scale, k_scale);
    // 5. attention -> y[:, :1024]   (tensor cores)
    attn_tc<<<dim3(LL/128, BB*HEADS), 256, ATTN_SMEM>>>(h, y);
    // 6. y[:, 1024:] = tanh(mlp @ w_mlp + b_mlp)   (4096 x 1024, K=4096)
    mma_gemm<1><<<dim3(HIDDEN/128, NTOK/128), 256, GEMM_SMEM>>>(
        h + 3*HIDDEN, W1N, w_mlp, HIDDEN, y + HIDDEN, 2*HIDDEN,
        MLPH, b_mlp, nullptr, nullptr);
    // 7. out = x + gate * (y @ w2 + b2)   (4096 x 1024, K=2048)
    mma_gemm<2><<<dim3(HIDDEN/128, NTOK/128), 256, GEMM_SMEM>>>(
        y, 2*HIDDEN, w2, HIDDEN, out, HIDDEN,
        2*HIDDEN, b2, x, mod);
}

// round 8
// speedup vs baseline: 7.3568x; 1.7420x over previous
#include <cuda_runtime.h>
#include <cuda_fp16.h>
#include <math.h>
#include <stdint.h>

#define HIDDEN   1024
#define HEADS    16
#define HEAD_DIM 64
#define MLPH     4096
#define BB       2
#define LL       2048
#define NTOK     (BB*LL)          // 4096
#define W1N      (3*HIDDEN+MLPH)  // 7168

// ---------------- scratch (static device globals; no runtime alloc) ------------
__device__ float  g_mod[BB*3*HIDDEN];                   // shift|scale|gate
__device__ __half g_xmod[NTOK*HIDDEN];                  // fp16 LN output
__device__ __half g_h[(size_t)NTOK*W1N];                // fp16 qkv|mlp
__device__ __half g_qh[(size_t)BB*HEADS*LL*HEAD_DIM];   // roped q (pre-scaled)
__device__ __half g_kh[(size_t)BB*HEADS*LL*HEAD_DIM];   // roped k
__device__ __half g_vh[(size_t)BB*HEADS*LL*HEAD_DIM];   // v
__device__ __half g_y[(size_t)NTOK*2*HIDDEN];           // attn | tanh-mlp (fp16)
__device__ __half g_w1t[(size_t)W1N*HIDDEN];            // w1^T  [7168][1024]
__device__ __half g_wmlpt[(size_t)HIDDEN*MLPH];         // w_mlp^T [1024][4096]
__device__ __half g_w2t[(size_t)HIDDEN*2*HIDDEN];       // w2^T  [1024][2048]

// =================== helpers ====================================================
__device__ __forceinline__ uint32_t smem_u32(const void* p) {
    uint32_t a;
    asm("{ .reg .u64 t; cvta.to.shared.u64 t, %1; cvt.u32.u64 %0, t; }"
        : "=r"(a) : "l"(p));
    return a;
}
__device__ __forceinline__ uint32_t pack_f16(float lo, float hi) {
    uint32_t r;
    asm("cvt.rn.f16x2.f32 %0, %1, %2;" : "=r"(r) : "f"(hi), "f"(lo));
    return r;
}
__device__ __forceinline__ void mma_f16(float* c, const uint32_t* a, const uint32_t* b) {
    asm volatile(
        "mma.sync.aligned.m16n8k16.row.col.f32.f16.f16.f32 "
        "{%0,%1,%2,%3}, {%4,%5,%6,%7}, {%8,%9}, {%0,%1,%2,%3};"
        : "+f"(c[0]), "+f"(c[1]), "+f"(c[2]), "+f"(c[3])
        : "r"(a[0]), "r"(a[1]), "r"(a[2]), "r"(a[3]), "r"(b[0]), "r"(b[1]));
}
__device__ __forceinline__ void cp16(uint32_t dst, const void* src) {
    asm volatile("cp.async.cg.shared.global [%0], [%1], 16;" :: "r"(dst), "l"(src));
}
__device__ __forceinline__ void cp_commit() {
    asm volatile("cp.async.commit_group;" ::: "memory");
}
template<int N>
__device__ __forceinline__ void cp_wait() {
    asm volatile("cp.async.wait_group %0;" :: "n"(N) : "memory");
}

// =================== transpose + convert: f32[K][N] -> f16[N][K] ================
__global__ void __launch_bounds__(256) transpose_h(
        const float* __restrict__ in, __half* __restrict__ out, int K, int N) {
    __shared__ float tile[32][33];
    const int n0 = blockIdx.x << 5, k0 = blockIdx.y << 5;
    const int tx = threadIdx.x, ty = threadIdx.y;
    #pragma unroll
    for (int i = 0; i < 4; i++)
        tile[ty + (i << 3)][tx] = in[(size_t)(k0 + ty + (i << 3)) * N + n0 + tx];
    __syncthreads();
    #pragma unroll
    for (int i = 0; i < 4; i++)
        out[(size_t)(n0 + ty + (i << 3)) * K + k0 + tx] =
            __float2half(tile[tx][ty + (i << 3)]);
}

// =================== fp16 GEMM: cp.async 3-stage, mma.sync m16n8k16 ============
// C[M,N] = epilogue(A[M,K]h @ Bt[N,K]h + bias)
// CTA 128x128x32, 8 warps (2x4), warp tile 64x32.
// MODE 0: +bias -> half    MODE 1: tanh(+bias) -> half
// MODE 2: x + gate*(+bias) -> float
static constexpr int PA = 40;                  // halves pitch (80 B)
static constexpr int TILE_B = 128 * PA * 2;    // 10240 B (one operand tile)
static constexpr int STAGE_B = 2 * TILE_B;     // 20480 B
static constexpr uint32_t GEMM_SMEM = 3 * STAGE_B;   // 61440 B

__device__ __forceinline__ void gemm_issue(
        const __half* __restrict__ A, int lda,
        const __half* __restrict__ Bt, int ldb,
        int bm, int bn, int kt, int slot, uint32_t sbase, int tid) {
    const uint32_t dA = sbase + slot * STAGE_B;
    const __half* Ag = A + (size_t)bm * lda + (kt << 5);
    #pragma unroll
    for (int i = 0; i < 2; i++) {
        int idx = (i << 8) + tid;
        int r = idx >> 2, q = idx & 3;
        cp16(dA + r * 80 + (q << 4), Ag + (size_t)r * lda + (q << 3));
    }
    const uint32_t dB = dA + TILE_B;
    const __half* Bg = Bt + (size_t)bn * ldb + (kt << 5);
    #pragma unroll
    for (int i = 0; i < 2; i++) {
        int idx = (i << 8) + tid;
        int r = idx >> 2, q = idx & 3;
        cp16(dB + r * 80 + (q << 4), Bg + (size_t)r * ldb + (q << 3));
    }
    cp_commit();
}

template<int MODE>
__global__ void __launch_bounds__(256, 2) mma_gemm(
        const __half* __restrict__ A, int lda,
        const __half* __restrict__ Bt, int ldb,
        void* __restrict__ Cv, int ldc, int K,
        const float* __restrict__ bias,
        const float* __restrict__ xres,
        const float* __restrict__ mod) {
    extern __shared__ char smc[];
    __half* const smh = (__half*)smc;
    const uint32_t sbase = smem_u32(smc);

    const int tid  = threadIdx.x;
    const int warp = tid >> 5;
    const int lane = tid & 31;
    const int g = lane >> 2, t = lane & 3;
    const int wm = (warp >> 2) * 64;
    const int wn = (warp & 3) * 32;
    const int bm = blockIdx.y << 7;
    const int bn = blockIdx.x << 7;

    float acc[4][4][4];
    #pragma unroll
    for (int i = 0; i < 4; i++)
        #pragma unroll
        for (int j = 0; j < 4; j++)
            #pragma unroll
            for (int e = 0; e < 4; e++) acc[i][j][e] = 0.0f;

    const int NT = K >> 5;
    gemm_issue(A, lda, Bt, ldb, bm, bn, 0, 0, sbase, tid);
    gemm_issue(A, lda, Bt, ldb, bm, bn, 1, 1, sbase, tid);

    for (int kt = 0; kt < NT; kt++) {
        if (kt + 1 < NT) cp_wait<1>(); else cp_wait<0>();
        __syncthreads();
        if (kt + 2 < NT)
            gemm_issue(A, lda, Bt, ldb, bm, bn, kt + 2, (kt + 2) % 3, sbase, tid);

        const __half* sA = smh + (kt % 3) * (STAGE_B / 2);
        const __half* sB = sA + TILE_B / 2;
        #pragma unroll
        for (int kk = 0; kk < 2; kk++) {
            const int c0 = (kk << 4) + (t << 1);
            uint32_t af[4][4], bf[4][2];
            #pragma unroll
            for (int mt = 0; mt < 4; mt++) {
                const __half* p = sA + (wm + (mt << 4) + g) * PA + c0;
                af[mt][0] = *(const uint32_t*)(p);
                af[mt][1] = *(const uint32_t*)(p + 8 * PA);
                af[mt][2] = *(const uint32_t*)(p + 8);
                af[mt][3] = *(const uint32_t*)(p + 8 * PA + 8);
            }
            #pragma unroll
            for (int nt = 0; nt < 4; nt++) {
                const __half* p = sB + (wn + (nt << 3) + g) * PA + c0;
                bf[nt][0] = *(const uint32_t*)(p);
                bf[nt][1] = *(const uint32_t*)(p + 8);
            }
            #pragma unroll
            for (int mt = 0; mt < 4; mt++)
                #pragma unroll
                for (int nt = 0; nt < 4; nt++)
                    mma_f16(acc[mt][nt], af[mt], bf[nt]);
        }
    }

    // ---- epilogue ----
    #pragma unroll
    for (int nt = 0; nt < 4; nt++) {
        const int col = bn + wn + (nt << 3) + (t << 1);
        const float2 bi = *(const float2*)(bias + col);
        #pragma unroll
        for (int mt = 0; mt < 4; mt++) {
            const int r0 = bm + wm + (mt << 4) + g;
            float2 v0, v1;
            v0.x = acc[mt][nt][0] + bi.x;  v0.y = acc[mt][nt][1] + bi.y;
            v1.x = acc[mt][nt][2] + bi.x;  v1.y = acc[mt][nt][3] + bi.y;
            if (MODE == 1) {
                v0.x = tanhf(v0.x); v0.y = tanhf(v0.y);
                v1.x = tanhf(v1.x); v1.y = tanhf(v1.y);
            }
            if (MODE == 2) {
                float* C = (float*)Cv;
                const int b0 = r0 >> 11;
                const float2 g2 = *(const float2*)(mod + b0*3*HIDDEN + 2*HIDDEN + col);
                const float2 x0 = *(const float2*)(xres + (size_t)r0*HIDDEN + col);
                const float2 x1 = *(const float2*)(xres + (size_t)(r0+8)*HIDDEN + col);
                v0.x = fmaf(g2.x, v0.x, x0.x); v0.y = fmaf(g2.y, v0.y, x0.y);
                v1.x = fmaf(g2.x, v1.x, x1.x); v1.y = fmaf(g2.y, v1.y, x1.y);
                *(float2*)(C + (size_t)r0 * ldc + col)       = v0;
                *(float2*)(C + (size_t)(r0 + 8) * ldc + col) = v1;
            } else {
                __half* C = (__half*)Cv;
                *(uint32_t*)(C + (size_t)r0 * ldc + col)       = pack_f16(v0.x, v0.y);
                *(uint32_t*)(C + (size_t)(r0 + 8) * ldc + col) = pack_f16(v1.x, v1.y);
            }
        }
    }
}

// =================== fp16 flash attention =======================================
// CTA: 128 q-rows, one (b,h). 8 warps x 16 rows. QK & PV fp16 mma, fp32 softmax.
static constexpr int PQ = 72;                        // halves pitch (144 B)
static constexpr int Q_BYTES  = 128 * PQ * 2;        // 18432
static constexpr int KV_BYTES = 64 * PQ * 2;         // 9216
static constexpr uint32_t ATTN_SMEM = Q_BYTES + 4 * KV_BYTES;  // 55296

__device__ __forceinline__ void attn_issue_kv(
        const __half* __restrict__ kh, const __half* __restrict__ vh,
        int kt, int slot, uint32_t sbase, int tid) {
    // 64 rows x 128 bytes each for K and V: 512 chunks of 16B per tensor,
    // 256 threads x 2 iterations.
    #pragma unroll
    for (int i = 0; i < 2; i++) {
        const int idx = (i << 8) + tid;          // 0..511
        const int r = idx >> 3, q = idx & 7;     // row 0..63, chunk 0..7
        const int row = (kt << 6) + r;
        const uint32_t dK = sbase + Q_BYTES + slot * KV_BYTES + r * 144 + (q << 4);
        cp16(dK,                kh + (size_t)row * 64 + (q << 3));
        cp16(dK + 2 * KV_BYTES, vh + (size_t)row * 64 + (q << 3));
    }
    cp_commit();
}

__global__ void __launch_bounds__(256, 2) attn_tc(
        const __half* __restrict__ qh, const __half* __restrict__ kh,
        const __half* __restrict__ vh, __half* __restrict__ y) {
    extern __shared__ char smc[];
    __half* const smh = (__half*)smc;
    const uint32_t sbase = smem_u32(smc);

    const int tid  = threadIdx.x;
    const int warp = tid >> 5;
    const int lane = tid & 31;
    const int g = lane >> 2, t = lane & 3;
    const int bh = blockIdx.y;
    const int q0 = blockIdx.x << 7;

    const __half* qb = qh + (size_t)bh * LL * HEAD_DIM;
    const __half* kb = kh + (size_t)bh * LL * HEAD_DIM;
    const __half* vb = vh + (size_t)bh * LL * HEAD_DIM;

    // stage Q tile (128 x 64 halves)
    #pragma unroll
    for (int i = 0; i < 4; i++) {
        int idx = (i << 8) + tid;
        int r = idx >> 3, q = idx & 7;
        *(uint4*)(smh + r * PQ + (q << 3)) =
            *(const uint4*)(qb + (size_t)(q0 + r) * 64 + (q << 3));
    }
    __syncthreads();
    uint32_t qa[4][4];
    #pragma unroll
    for (int kk = 0; kk < 4; kk++) {
        const __half* p = smh + ((warp << 4) + g) * PQ + (kk << 4) + (t << 1);
        qa[kk][0] = *(const uint32_t*)(p);
        qa[kk][1] = *(const uint32_t*)(p + 8 * PQ);
        qa[kk][2] = *(const uint32_t*)(p + 8);
        qa[kk][3] = *(const uint32_t*)(p + 8 * PQ + 8);
    }
    __syncthreads();

    float o[8][4];
    #pragma unroll
    for (int dn = 0; dn < 8; dn++)
        #pragma unroll
        for (int e = 0; e < 4; e++) o[dn][e] = 0.0f;
    float m0 = -1e30f, m1 = -1e30f, l0 = 0.0f, l1 = 0.0f;

    attn_issue_kv(kb, vb, 0, 0, sbase, tid);

    const int NT = LL / 64;
    for (int kt = 0; kt < NT; kt++) {
        cp_wait<0>();
        __syncthreads();
        if (kt + 1 < NT)
            attn_issue_kv(kb, vb, kt + 1, (kt + 1) & 1, sbase, tid);

        const __half* sK = smh + Q_BYTES / 2 + (kt & 1) * (KV_BYTES / 2);
        const __half* sV = sK + KV_BYTES;   // +2*KV_BYTES bytes

        // S = Q @ K^T
        float s[8][4];
        #pragma unroll
        for (int nt = 0; nt < 8; nt++)
            #pragma unroll
            for (int e = 0; e < 4; e++) s[nt][e] = 0.0f;
        #pragma unroll
        for (int kk = 0; kk < 4; kk++) {
            const int c0 = (kk << 4) + (t << 1);
            #pragma unroll
            for (int nt = 0; nt < 8; nt++) {
                const __half* p = sK + ((nt << 3) + g) * PQ + c0;
                uint32_t kf[2];
                kf[0] = *(const uint32_t*)(p);
                kf[1] = *(const uint32_t*)(p + 8);
                mma_f16(s[nt], qa[kk], kf);
            }
        }

        // online softmax (rows g, g+8)
        float mx0 = -1e30f, mx1 = -1e30f;
        #pragma unroll
        for (int nt = 0; nt < 8; nt++) {
            mx0 = fmaxf(mx0, fmaxf(s[nt][0], s[nt][1]));
            mx1 = fmaxf(mx1, fmaxf(s[nt][2], s[nt][3]));
        }
        mx0 = fmaxf(mx0, __shfl_xor_sync(0xffffffffu, mx0, 1));
        mx0 = fmaxf(mx0, __shfl_xor_sync(0xffffffffu, mx0, 2));
        mx1 = fmaxf(mx1, __shfl_xor_sync(0xffffffffu, mx1, 1));
        mx1 = fmaxf(mx1, __shfl_xor_sync(0xffffffffu, mx1, 2));
        const float M0 = fmaxf(m0, mx0), M1 = fmaxf(m1, mx1);
        const float f0 = __expf(m0 - M0), f1 = __expf(m1 - M1);
        m0 = M0; m1 = M1;

        float sum0 = 0.0f, sum1 = 0.0f;
        #pragma unroll
        for (int nt = 0; nt < 8; nt++) {
            s[nt][0] = __expf(s[nt][0] - M0);
            s[nt][1] = __expf(s[nt][1] - M0);
            s[nt][2] = __expf(s[nt][2] - M1);
            s[nt][3] = __expf(s[nt][3] - M1);
            sum0 += s[nt][0] + s[nt][1];
            sum1 += s[nt][2] + s[nt][3];
        }
        sum0 += __shfl_xor_sync(0xffffffffu, sum0, 1);
        sum0 += __shfl_xor_sync(0xffffffffu, sum0, 2);
        sum1 += __shfl_xor_sync(0xffffffffu, sum1, 1);
        sum1 += __shfl_xor_sync(0xffffffffu, sum1, 2);
        l0 = l0 * f0 + sum0;
        l1 = l1 * f1 + sum1;

        #pragma unroll
        for (int dn = 0; dn < 8; dn++) {
            o[dn][0] *= f0; o[dn][1] *= f0;
            o[dn][2] *= f1; o[dn][3] *= f1;
        }

        // P -> fp16 a-frags
        uint32_t pa[4][4];
        #pragma unroll
        for (int kc = 0; kc < 4; kc++) {
            pa[kc][0] = pack_f16(s[2*kc][0],   s[2*kc][1]);
            pa[kc][1] = pack_f16(s[2*kc][2],   s[2*kc][3]);
            pa[kc][2] = pack_f16(s[2*kc+1][0], s[2*kc+1][1]);
            pa[kc][3] = pack_f16(s[2*kc+1][2], s[2*kc+1][3]);
        }

        // O += P @ V
        #pragma unroll
        for (int kc = 0; kc < 4; kc++) {
            const int kr = (kc << 4) + (t << 1);
            #pragma unroll
            for (int dn = 0; dn < 8; dn++) {
                const int dcol = (dn << 3) + g;
                uint32_t vf[2];
                uint32_t a0 = *(const uint16_t*)(sV + (kr    ) * PQ + dcol);
                uint32_t a1 = *(const uint16_t*)(sV + (kr + 1) * PQ + dcol);
                uint32_t a2 = *(const uint16_t*)(sV + (kr + 8) * PQ + dcol);
                uint32_t a3 = *(const uint16_t*)(sV + (kr + 9) * PQ + dcol);
                vf[0] = a0 | (a1 << 16);
                vf[1] = a2 | (a3 << 16);
                mma_f16(o[dn], pa[kc], vf);
            }
        }
        __syncthreads();
    }

    // write O (fp16) to y[:, :1024]
    const float il0 = 1.0f / l0, il1 = 1.0f / l1;
    const int hd = bh & 15;
    const int row0 = (bh >> 4) * LL + q0 + (warp << 4) + g;
    __half* yp0 = y + (size_t)row0 * (2*HIDDEN) + hd * HEAD_DIM + (t << 1);
    __half* yp1 = yp0 + (size_t)8 * (2*HIDDEN);
    #pragma unroll
    for (int dn = 0; dn < 8; dn++) {
        *(uint32_t*)(yp0 + (dn << 3)) = pack_f16(o[dn][0] * il0, o[dn][1] * il0);
        *(uint32_t*)(yp1 + (dn << 3)) = pack_f16(o[dn][2] * il1, o[dn][3] * il1);
    }
}

// ---------------- kernel 1: mod = silu(vec) @ w_mod + b_mod --------------------
__global__ void mod_kernel(const float* __restrict__ vec,
                           const float* __restrict__ w_mod,
                           const float* __restrict__ b_mod,
                           float* __restrict__ mod) {
    __shared__ float sv[HIDDEN];
    int b = blockIdx.y;
    int n = blockIdx.x * 128 + threadIdx.x;
    for (int i = threadIdx.x; i < HIDDEN; i += 128) {
        float v = vec[b*HIDDEN + i];
        sv[i] = v / (1.0f + expf(-v));
    }
    __syncthreads();
    float acc = b_mod[n];
    #pragma unroll 8
    for (int k = 0; k < HIDDEN; k++)
        acc = fmaf(sv[k], w_mod[(size_t)k*3*HIDDEN + n], acc);
    mod[b*3*HIDDEN + n] = acc;
}

// ---------------- kernel 2: layernorm + modulate -> fp16 ------------------------
__global__ void __launch_bounds__(256) ln_mod_kernel(const float* __restrict__ x,
                                                     const float* __restrict__ mod,
                                                     __half* __restrict__ xmod) {
    __shared__ float sbuf[8];
    __shared__ float s_mean, s_rstd;
    int token = blockIdx.x;
    int b = token >> 11;
    int tid = threadIdx.x;
    const float4 xv = ((const float4*)(x + (size_t)token*HIDDEN))[tid];

    float s = xv.x + xv.y + xv.z + xv.w;
    #pragma unroll
    for (int o = 16; o > 0; o >>= 1) s += __shfl_xor_sync(0xffffffffu, s, o);
    if ((tid & 31) == 0) sbuf[tid >> 5] = s;
    __syncthreads();
    if (tid == 0) {
        float tq = 0;
        #pragma unroll
        for (int i = 0; i < 8; i++) tq += sbuf[i];
        s_mean = tq * (1.0f / HIDDEN);
    }
    __syncthreads();
    float m = s_mean;
    float dx = xv.x - m, dy = xv.y - m, dz = xv.z - m, dw = xv.w - m;
    float ss = dx*dx + dy*dy + dz*dz + dw*dw;
    #pragma unroll
    for (int o = 16; o > 0; o >>= 1) ss += __shfl_xor_sync(0xffffffffu, ss, o);
    __syncthreads();
    if ((tid & 31) == 0) sbuf[tid >> 5] = ss;
    __syncthreads();
    if (tid == 0) {
        float tq = 0;
        #pragma unroll
        for (int i = 0; i < 8; i++) tq += sbuf[i];
        s_rstd = rsqrtf(tq * (1.0f / HIDDEN) + 1e-6f);
    }
    __syncthreads();
    float r = s_rstd;
    int c = tid * 4;
    const float4 sh = *(const float4*)(mod + b*3*HIDDEN + c);
    const float4 sc = *(const float4*)(mod + b*3*HIDDEN + HIDDEN + c);
    float o0 = fmaf(1.0f + sc.x, dx*r, sh.x);
    float o1 = fmaf(1.0f + sc.y, dy*r, sh.y);
    float o2 = fmaf(1.0f + sc.z, dz*r, sh.z);
    float o3 = fmaf(1.0f + sc.w, dw*r, sh.w);
    uint32_t* dst = (uint32_t*)(xmod + (size_t)token*HIDDEN + c);
    dst[0] = pack_f16(o0, o1);
    dst[1] = pack_f16(o2, o3);
}

// ---------------- kernel 4: RMSNorm + RoPE, fp16 h -> per-head q/k/v ------------
__global__ void __launch_bounds__(512) qk_norm_rope_kernel(
        const __half* __restrict__ h,
        const float* __restrict__ pe,
        const float* __restrict__ q_scale,
        const float* __restrict__ k_scale,
        __half* __restrict__ qh, __half* __restrict__ kh, __half* __restrict__ vh) {
    int token = blockIdx.x;
    int l = token & (LL - 1);
    int b = token >> 11;
    int head = threadIdx.x >> 5;
    int lane = threadIdx.x & 31;

    const __half* hq = h + (size_t)token*W1N + head*HEAD_DIM;
    const size_t oidx = ((size_t)(b*HEADS + head)*LL + l)*HEAD_DIM + lane*2;

    const float4 p = *(const float4*)(pe + (size_t)l*128 + lane*4);
    float sx = q_scale[lane*2], sy = q_scale[lane*2+1];
    float kx = k_scale[lane*2], ky = k_scale[lane*2+1];

    {
        float2 q2 = __half22float2(*(const __half2*)(hq + lane*2));
        float ss = q2.x*q2.x + q2.y*q2.y;
        #pragma unroll
        for (int o = 16; o > 0; o >>= 1) ss += __shfl_xor_sync(0xffffffffu, ss, o);
        float rr = rsqrtf(ss * (1.0f/HEAD_DIM) + 1e-6f);
        float t0 = q2.x * rr * sx, t1 = q2.y * rr * sy;
        *(uint32_t*)(qh + oidx) =
            pack_f16(0.125f*(p.x*t0 + p.y*t1), 0.125f*(p.z*t0 + p.w*t1));
    }
    {
        float2 k2 = __half22float2(*(const __half2*)(hq + HIDDEN + lane*2));
        float ss = k2.x*k2.x + k2.y*k2.y;
        #pragma unroll
        for (int o = 16; o > 0; o >>= 1) ss += __shfl_xor_sync(0xffffffffu, ss, o);
        float rr = rsqrtf(ss * (1.0f/HEAD_DIM) + 1e-6f);
        float t0 = k2.x * rr * kx, t1 = k2.y * rr * ky;
        *(uint32_t*)(kh + oidx) = pack_f16(p.x*t0 + p.y*t1, p.z*t0 + p.w*t1);
    }
    *(__half2*)(vh + oidx) = *(const __half2*)(hq + 2*HIDDEN + lane*2);
}

// ---------------- launch --------------------------------------------------------
extern "C" void kernel_launch(void* const* d_in, const int* in_sizes, int n_in,
                              void* d_out, int out_size) {
    const float* x       = (const float*)d_in[0];
    const float* vec     = (const float*)d_in[1];
    const float* pe      = (const float*)d_in[2];
    const float* w_mod   = (const float*)d_in[3];
    const float* b_mod   = (const float*)d_in[4];
    const float* w1      = (const float*)d_in[5];
    const float* b1      = (const float*)d_in[6];
    const float* w_mlp   = (const float*)d_in[7];
    const float* b_mlp   = (const float*)d_in[8];
    const float* w2      = (const float*)d_in[9];
    const float* b2      = (const float*)d_in[10];
    const float* q_scale = (const float*)d_in[11];
    const float* k_scale = (const float*)d_in[12];
    float* out = (float*)d_out;

    float *mod;
    __half *xmod, *h, *qh, *kh, *vh, *y, *w1t, *wmlpt, *w2t;
    cudaGetSymbolAddress((void**)&mod,   g_mod);
    cudaGetSymbolAddress((void**)&xmod,  g_xmod);
    cudaGetSymbolAddress((void**)&h,     g_h);
    cudaGetSymbolAddress((void**)&qh,    g_qh);
    cudaGetSymbolAddress((void**)&kh,    g_kh);
    cudaGetSymbolAddress((void**)&vh,    g_vh);
    cudaGetSymbolAddress((void**)&y,     g_y);
    cudaGetSymbolAddress((void**)&w1t,   g_w1t);
    cudaGetSymbolAddress((void**)&wmlpt, g_wmlpt);
    cudaGetSymbolAddress((void**)&w2t,   g_w2t);

    cudaFuncSetAttribute(mma_gemm<0>, cudaFuncAttributeMaxDynamicSharedMemorySize, GEMM_SMEM);
    cudaFuncSetAttribute(mma_gemm<1>, cudaFuncAttributeMaxDynamicSharedMemorySize, GEMM_SMEM);
    cudaFuncSetAttribute(mma_gemm<2>, cudaFuncAttributeMaxDynamicSharedMemorySize, GEMM_SMEM);
    cudaFuncSetAttribute(attn_tc,     cudaFuncAttributeMaxDynamicSharedMemorySize, ATTN_SMEM);

    // 0. weight transposes -> fp16 [N][K]
    transpose_h<<<dim3(W1N/32,   HIDDEN/32),  dim3(32,8)>>>(w1,    w1t,   HIDDEN, W1N);
    transpose_h<<<dim3(HIDDEN/32, MLPH/32),   dim3(32,8)>>>(w_mlp, wmlpt, MLPH,   HIDDEN);
    transpose_h<<<dim3(HIDDEN/32, 2*HIDDEN/32), dim3(32,8)>>>(w2,  w2t,   2*HIDDEN, HIDDEN);
    // 1. modulation vector
    mod_kernel<<<dim3(3*HIDDEN/128, BB), 128>>>(vec, w_mod, b_mod, mod);
    // 2. layernorm + modulate -> fp16
    ln_mod_kernel<<<NTOK, 256>>>(x, mod, xmod);
    // 3. h = x_mod @ w1 + b1  -> fp16
    mma_gemm<0><<<dim3(W1N/128, NTOK/128), 256, GEMM_SMEM>>>(
        xmod, HIDDEN, w1t, HIDDEN, h, W1N, HIDDEN, b1, nullptr, nullptr);
    // 4. q,k rmsnorm + rope -> per-head fp16 buffers
    qk_norm_rope_kernel<<<NTOK, 512>>>(h, pe, q_scale, k_scale, qh, kh, vh);
    // 5. attention -> y[:, :1024] (fp16)
    attn_tc<<<dim3(LL/128, BB*HEADS), 256, ATTN_SMEM>>>(qh, kh, vh, y);
    // 6. y[:, 1024:] = tanh(mlp @ w_mlp + b_mlp) (fp16)
    mma_gemm<1><<<dim3(HIDDEN/128, NTOK/128), 256, GEMM_SMEM>>>(
        h + 3*HIDDEN, W1N, wmlpt, MLPH, y + HIDDEN, 2*HIDDEN,
        MLPH, b_mlp, nullptr, nullptr);
    // 7. out = x + gate * (y @ w2 + b2)  (fp32)
    mma_gemm<2><<<dim3(HIDDEN/128, NTOK/128), 256, GEMM_SMEM>>>(
        y, 2*HIDDEN, w2t, 2*HIDDEN, out, HIDDEN,
        2*HIDDEN, b2, x, mod);
}

// round 9
// speedup vs baseline: 9.0643x; 1.2321x over previous
#include <cuda_runtime.h>
#include <cuda_fp16.h>
#include <math.h>
#include <stdint.h>

#define HIDDEN   1024
#define HEADS    16
#define HEAD_DIM 64
#define MLPH     4096
#define BB       2
#define LL       2048
#define NTOK     (BB*LL)          // 4096
#define W1N      (3*HIDDEN+MLPH)  // 7168

// ---------------- scratch (static device globals; no runtime alloc) ------------
__device__ float  g_mod[BB*3*HIDDEN];                   // shift|scale|gate
__device__ float  g_modp[8*BB*3*HIDDEN];                // split-K partials
__device__ __half g_xmod[NTOK*HIDDEN];                  // fp16 LN output
__device__ __half g_h[(size_t)NTOK*W1N];                // fp16 qkv|mlp
__device__ __half g_qh[(size_t)BB*HEADS*LL*HEAD_DIM];   // roped q (pre-scaled)
__device__ __half g_kh[(size_t)BB*HEADS*LL*HEAD_DIM];   // roped k
__device__ __half g_vh[(size_t)BB*HEADS*LL*HEAD_DIM];   // v
__device__ __half g_y[(size_t)NTOK*2*HIDDEN];           // attn | tanh-mlp (fp16)
__device__ __half g_w1t[(size_t)W1N*HIDDEN];            // w1^T  [7168][1024]
__device__ __half g_wmlpt[(size_t)HIDDEN*MLPH];         // w_mlp^T [1024][4096]
__device__ __half g_w2t[(size_t)HIDDEN*2*HIDDEN];       // w2^T  [1024][2048]

// =================== helpers ====================================================
__device__ __forceinline__ uint32_t smem_u32(const void* p) {
    uint32_t a;
    asm("{ .reg .u64 t; cvta.to.shared.u64 t, %1; cvt.u32.u64 %0, t; }"
        : "=r"(a) : "l"(p));
    return a;
}
__device__ __forceinline__ uint32_t pack_f16(float lo, float hi) {
    uint32_t r;
    asm("cvt.rn.f16x2.f32 %0, %1, %2;" : "=r"(r) : "f"(hi), "f"(lo));
    return r;
}
__device__ __forceinline__ void mma_f16(float* c, const uint32_t* a, const uint32_t* b) {
    asm volatile(
        "mma.sync.aligned.m16n8k16.row.col.f32.f16.f16.f32 "
        "{%0,%1,%2,%3}, {%4,%5,%6,%7}, {%8,%9}, {%0,%1,%2,%3};"
        : "+f"(c[0]), "+f"(c[1]), "+f"(c[2]), "+f"(c[3])
        : "r"(a[0]), "r"(a[1]), "r"(a[2]), "r"(a[3]), "r"(b[0]), "r"(b[1]));
}
__device__ __forceinline__ void ldm_x4(uint32_t* r, uint32_t addr) {
    asm volatile("ldmatrix.sync.aligned.m8n8.x4.shared.b16 {%0,%1,%2,%3}, [%4];"
        : "=r"(r[0]), "=r"(r[1]), "=r"(r[2]), "=r"(r[3]) : "r"(addr));
}
__device__ __forceinline__ void ldm_x4_t(uint32_t* r, uint32_t addr) {
    asm volatile("ldmatrix.sync.aligned.m8n8.x4.trans.shared.b16 {%0,%1,%2,%3}, [%4];"
        : "=r"(r[0]), "=r"(r[1]), "=r"(r[2]), "=r"(r[3]) : "r"(addr));
}
__device__ __forceinline__ void cp16(uint32_t dst, const void* src) {
    asm volatile("cp.async.cg.shared.global [%0], [%1], 16;" :: "r"(dst), "l"(src));
}
__device__ __forceinline__ void cp_commit() {
    asm volatile("cp.async.commit_group;" ::: "memory");
}
template<int N>
__device__ __forceinline__ void cp_wait() {
    asm volatile("cp.async.wait_group %0;" :: "n"(N) : "memory");
}

// =================== transpose + convert: f32[K][N] -> f16[N][K] ================
__global__ void __launch_bounds__(256) transpose_h(
        const float* __restrict__ in, __half* __restrict__ out, int K, int N) {
    __shared__ float tile[32][33];
    const int n0 = blockIdx.x << 5, k0 = blockIdx.y << 5;
    const int tx = threadIdx.x, ty = threadIdx.y;
    #pragma unroll
    for (int i = 0; i < 4; i++)
        tile[ty + (i << 3)][tx] = in[(size_t)(k0 + ty + (i << 3)) * N + n0 + tx];
    __syncthreads();
    #pragma unroll
    for (int i = 0; i < 4; i++)
        out[(size_t)(n0 + ty + (i << 3)) * K + k0 + tx] =
            __float2half(tile[tx][ty + (i << 3)]);
}

// =================== fp16 GEMM: cp.async 3-stage, ldmatrix, mma m16n8k16 =======
static constexpr int PA = 40;                  // halves pitch (80 B)
static constexpr int TILE_B = 128 * PA * 2;    // 10240 B
static constexpr int STAGE_B = 2 * TILE_B;     // 20480 B
static constexpr uint32_t GEMM_SMEM = 3 * STAGE_B;   // 61440 B

__device__ __forceinline__ void gemm_issue(
        const __half* __restrict__ A, int lda,
        const __half* __restrict__ Bt, int ldb,
        int bm, int bn, int kt, int slot, uint32_t sbase, int tid) {
    const uint32_t dA = sbase + slot * STAGE_B;
    const __half* Ag = A + (size_t)bm * lda + (kt << 5);
    #pragma unroll
    for (int i = 0; i < 2; i++) {
        int idx = (i << 8) + tid;
        int r = idx >> 2, q = idx & 3;
        cp16(dA + r * 80 + (q << 4), Ag + (size_t)r * lda + (q << 3));
    }
    const uint32_t dB = dA + TILE_B;
    const __half* Bg = Bt + (size_t)bn * ldb + (kt << 5);
    #pragma unroll
    for (int i = 0; i < 2; i++) {
        int idx = (i << 8) + tid;
        int r = idx >> 2, q = idx & 3;
        cp16(dB + r * 80 + (q << 4), Bg + (size_t)r * ldb + (q << 3));
    }
    cp_commit();
}

template<int MODE>
__global__ void __launch_bounds__(256, 2) mma_gemm(
        const __half* __restrict__ A, int lda,
        const __half* __restrict__ Bt, int ldb,
        void* __restrict__ Cv, int ldc, int K,
        const float* __restrict__ bias,
        const float* __restrict__ xres,
        const float* __restrict__ mod) {
    extern __shared__ char smc[];
    const uint32_t sbase = smem_u32(smc);

    const int tid  = threadIdx.x;
    const int warp = tid >> 5;
    const int lane = tid & 31;
    const int g = lane >> 2, t = lane & 3;
    const int wm = (warp >> 2) * 64;
    const int wn = (warp & 3) * 32;
    const int bm = blockIdx.y << 7;
    const int bn = blockIdx.x << 7;

    // ldmatrix per-lane address offsets (byte offsets within tile)
    const int rA = (lane & 7) + ((lane >> 3) & 1) * 8;   // row off
    const int cA = (lane >> 4) * 8;                      // col off (halves)
    const int rB = (lane & 7) + (lane >> 4) * 8;
    const int cB = ((lane >> 3) & 1) * 8;
    const uint32_t aoff = ((wm + rA) * PA + cA) * 2;
    const uint32_t boff = ((wn + rB) * PA + cB) * 2;

    float acc[4][4][4];
    #pragma unroll
    for (int i = 0; i < 4; i++)
        #pragma unroll
        for (int j = 0; j < 4; j++)
            #pragma unroll
            for (int e = 0; e < 4; e++) acc[i][j][e] = 0.0f;

    const int NT = K >> 5;
    gemm_issue(A, lda, Bt, ldb, bm, bn, 0, 0, sbase, tid);
    gemm_issue(A, lda, Bt, ldb, bm, bn, 1, 1, sbase, tid);

    for (int kt = 0; kt < NT; kt++) {
        if (kt + 1 < NT) cp_wait<1>(); else cp_wait<0>();
        __syncthreads();
        if (kt + 2 < NT)
            gemm_issue(A, lda, Bt, ldb, bm, bn, kt + 2, (kt + 2) % 3, sbase, tid);

        const uint32_t sA_b = sbase + (kt % 3) * STAGE_B;
        const uint32_t sB_b = sA_b + TILE_B;
        #pragma unroll
        for (int kk = 0; kk < 2; kk++) {
            uint32_t af[4][4], bf[4][2];
            #pragma unroll
            for (int mt = 0; mt < 4; mt++)
                ldm_x4(af[mt], sA_b + aoff + ((mt * 16 * PA + kk * 16) << 1));
            #pragma unroll
            for (int ntp = 0; ntp < 2; ntp++) {
                uint32_t tmp[4];
                ldm_x4(tmp, sB_b + boff + ((ntp * 16 * PA + kk * 16) << 1));
                bf[2*ntp][0]   = tmp[0]; bf[2*ntp][1]   = tmp[1];
                bf[2*ntp+1][0] = tmp[2]; bf[2*ntp+1][1] = tmp[3];
            }
            #pragma unroll
            for (int mt = 0; mt < 4; mt++)
                #pragma unroll
                for (int nt = 0; nt < 4; nt++)
                    mma_f16(acc[mt][nt], af[mt], bf[nt]);
        }
    }

    // ---- epilogue ----
    #pragma unroll
    for (int nt = 0; nt < 4; nt++) {
        const int col = bn + wn + (nt << 3) + (t << 1);
        const float2 bi = *(const float2*)(bias + col);
        #pragma unroll
        for (int mt = 0; mt < 4; mt++) {
            const int r0 = bm + wm + (mt << 4) + g;
            float2 v0, v1;
            v0.x = acc[mt][nt][0] + bi.x;  v0.y = acc[mt][nt][1] + bi.y;
            v1.x = acc[mt][nt][2] + bi.x;  v1.y = acc[mt][nt][3] + bi.y;
            if (MODE == 1) {
                v0.x = tanhf(v0.x); v0.y = tanhf(v0.y);
                v1.x = tanhf(v1.x); v1.y = tanhf(v1.y);
            }
            if (MODE == 2) {
                float* C = (float*)Cv;
                const int b0 = r0 >> 11;
                const float2 g2 = *(const float2*)(mod + b0*3*HIDDEN + 2*HIDDEN + col);
                const float2 x0 = *(const float2*)(xres + (size_t)r0*HIDDEN + col);
                const float2 x1 = *(const float2*)(xres + (size_t)(r0+8)*HIDDEN + col);
                v0.x = fmaf(g2.x, v0.x, x0.x); v0.y = fmaf(g2.y, v0.y, x0.y);
                v1.x = fmaf(g2.x, v1.x, x1.x); v1.y = fmaf(g2.y, v1.y, x1.y);
                *(float2*)(C + (size_t)r0 * ldc + col)       = v0;
                *(float2*)(C + (size_t)(r0 + 8) * ldc + col) = v1;
            } else {
                __half* C = (__half*)Cv;
                *(uint32_t*)(C + (size_t)r0 * ldc + col)       = pack_f16(v0.x, v0.y);
                *(uint32_t*)(C + (size_t)(r0 + 8) * ldc + col) = pack_f16(v1.x, v1.y);
            }
        }
    }
}

// =================== fp16 flash attention (ldmatrix frags) ======================
static constexpr int PQ = 72;                        // halves pitch (144 B)
static constexpr int Q_BYTES  = 128 * PQ * 2;        // 18432
static constexpr int KV_BYTES = 64 * PQ * 2;         // 9216
static constexpr uint32_t ATTN_SMEM = Q_BYTES + 4 * KV_BYTES;  // 55296

__device__ __forceinline__ void attn_issue_kv(
        const __half* __restrict__ kh, const __half* __restrict__ vh,
        int kt, int slot, uint32_t sbase, int tid) {
    #pragma unroll
    for (int i = 0; i < 2; i++) {
        const int idx = (i << 8) + tid;          // 0..511
        const int r = idx >> 3, q = idx & 7;     // row 0..63, 16B chunk 0..7
        const int row = (kt << 6) + r;
        const uint32_t dK = sbase + Q_BYTES + slot * KV_BYTES + r * 144 + (q << 4);
        cp16(dK,                kh + (size_t)row * 64 + (q << 3));
        cp16(dK + 2 * KV_BYTES, vh + (size_t)row * 64 + (q << 3));
    }
    cp_commit();
}

__global__ void __launch_bounds__(256, 2) attn_tc(
        const __half* __restrict__ qh, const __half* __restrict__ kh,
        const __half* __restrict__ vh, __half* __restrict__ y) {
    extern __shared__ char smc[];
    __half* const smh = (__half*)smc;
    const uint32_t sbase = smem_u32(smc);

    const int tid  = threadIdx.x;
    const int warp = tid >> 5;
    const int lane = tid & 31;
    const int g = lane >> 2, t = lane & 3;
    const int bh = blockIdx.y;
    const int q0 = blockIdx.x << 7;

    const __half* qb = qh + (size_t)bh * LL * HEAD_DIM;
    const __half* kb = kh + (size_t)bh * LL * HEAD_DIM;
    const __half* vb = vh + (size_t)bh * LL * HEAD_DIM;

    // ldmatrix per-lane offsets
    const int rK = (lane & 7) + (lane >> 4) * 8;          // K (non-trans, B-style)
    const int cK = ((lane >> 3) & 1) * 8;
    const int rV = (lane & 7) + ((lane >> 3) & 1) * 8;    // V (trans)
    const int cV = (lane >> 4) * 8;
    const uint32_t koff = (rK * PQ + cK) * 2;
    const uint32_t voff = (rV * PQ + cV) * 2;

    // stage Q tile (128 x 64 halves)
    #pragma unroll
    for (int i = 0; i < 4; i++) {
        int idx = (i << 8) + tid;
        int r = idx >> 3, q = idx & 7;
        *(uint4*)(smh + r * PQ + (q << 3)) =
            *(const uint4*)(qb + (size_t)(q0 + r) * 64 + (q << 3));
    }
    __syncthreads();
    uint32_t qa[4][4];
    {
        const uint32_t qoff = (((warp << 4) + rV) * PQ + cV) * 2;  // A-style = rV/cV
        #pragma unroll
        for (int kk = 0; kk < 4; kk++)
            ldm_x4(qa[kk], sbase + qoff + ((kk * 16) << 1));
    }
    __syncthreads();

    float o[8][4];
    #pragma unroll
    for (int dn = 0; dn < 8; dn++)
        #pragma unroll
        for (int e = 0; e < 4; e++) o[dn][e] = 0.0f;
    float m0 = -1e30f, m1 = -1e30f, l0 = 0.0f, l1 = 0.0f;

    attn_issue_kv(kb, vb, 0, 0, sbase, tid);

    const int NT = LL / 64;
    for (int kt = 0; kt < NT; kt++) {
        cp_wait<0>();
        __syncthreads();
        if (kt + 1 < NT)
            attn_issue_kv(kb, vb, kt + 1, (kt + 1) & 1, sbase, tid);

        const uint32_t sK_b = sbase + Q_BYTES + (kt & 1) * KV_BYTES;
        const uint32_t sV_b = sK_b + 2 * KV_BYTES;

        // S = Q @ K^T
        float s[8][4];
        #pragma unroll
        for (int nt = 0; nt < 8; nt++)
            #pragma unroll
            for (int e = 0; e < 4; e++) s[nt][e] = 0.0f;
        #pragma unroll
        for (int kk = 0; kk < 4; kk++) {
            uint32_t kf[8][2];
            #pragma unroll
            for (int ntp = 0; ntp < 4; ntp++) {
                uint32_t tmp[4];
                ldm_x4(tmp, sK_b + koff + ((ntp * 16 * PQ + kk * 16) << 1));
                kf[2*ntp][0]   = tmp[0]; kf[2*ntp][1]   = tmp[1];
                kf[2*ntp+1][0] = tmp[2]; kf[2*ntp+1][1] = tmp[3];
            }
            #pragma unroll
            for (int nt = 0; nt < 8; nt++)
                mma_f16(s[nt], qa[kk], kf[nt]);
        }

        // online softmax (rows g, g+8)
        float mx0 = -1e30f, mx1 = -1e30f;
        #pragma unroll
        for (int nt = 0; nt < 8; nt++) {
            mx0 = fmaxf(mx0, fmaxf(s[nt][0], s[nt][1]));
            mx1 = fmaxf(mx1, fmaxf(s[nt][2], s[nt][3]));
        }
        mx0 = fmaxf(mx0, __shfl_xor_sync(0xffffffffu, mx0, 1));
        mx0 = fmaxf(mx0, __shfl_xor_sync(0xffffffffu, mx0, 2));
        mx1 = fmaxf(mx1, __shfl_xor_sync(0xffffffffu, mx1, 1));
        mx1 = fmaxf(mx1, __shfl_xor_sync(0xffffffffu, mx1, 2));
        const float M0 = fmaxf(m0, mx0), M1 = fmaxf(m1, mx1);
        const float f0 = __expf(m0 - M0), f1 = __expf(m1 - M1);
        m0 = M0; m1 = M1;

        float sum0 = 0.0f, sum1 = 0.0f;
        #pragma unroll
        for (int nt = 0; nt < 8; nt++) {
            s[nt][0] = __expf(s[nt][0] - M0);
            s[nt][1] = __expf(s[nt][1] - M0);
            s[nt][2] = __expf(s[nt][2] - M1);
            s[nt][3] = __expf(s[nt][3] - M1);
            sum0 += s[nt][0] + s[nt][1];
            sum1 += s[nt][2] + s[nt][3];
        }
        sum0 += __shfl_xor_sync(0xffffffffu, sum0, 1);
        sum0 += __shfl_xor_sync(0xffffffffu, sum0, 2);
        sum1 += __shfl_xor_sync(0xffffffffu, sum1, 1);
        sum1 += __shfl_xor_sync(0xffffffffu, sum1, 2);
        l0 = l0 * f0 + sum0;
        l1 = l1 * f1 + sum1;

        #pragma unroll
        for (int dn = 0; dn < 8; dn++) {
            o[dn][0] *= f0; o[dn][1] *= f0;
            o[dn][2] *= f1; o[dn][3] *= f1;
        }

        // P -> fp16 a-frags
        uint32_t pa[4][4];
        #pragma unroll
        for (int kc = 0; kc < 4; kc++) {
            pa[kc][0] = pack_f16(s[2*kc][0],   s[2*kc][1]);
            pa[kc][1] = pack_f16(s[2*kc][2],   s[2*kc][3]);
            pa[kc][2] = pack_f16(s[2*kc+1][0], s[2*kc+1][1]);
            pa[kc][3] = pack_f16(s[2*kc+1][2], s[2*kc+1][3]);
        }

        // O += P @ V  (V b-frags via ldmatrix.trans)
        #pragma unroll
        for (int kc = 0; kc < 4; kc++) {
            #pragma unroll
            for (int dnp = 0; dnp < 4; dnp++) {
                uint32_t tmp[4];
                ldm_x4_t(tmp, sV_b + voff + ((kc * 16 * PQ + dnp * 16) << 1));
                mma_f16(o[2*dnp],   pa[kc], tmp);        // {tmp[0],tmp[1]}
                mma_f16(o[2*dnp+1], pa[kc], tmp + 2);    // {tmp[2],tmp[3]}
            }
        }
        __syncthreads();
    }

    // write O (fp16) to y[:, :1024]
    const float il0 = 1.0f / l0, il1 = 1.0f / l1;
    const int hd = bh & 15;
    const int row0 = (bh >> 4) * LL + q0 + (warp << 4) + g;
    __half* yp0 = y + (size_t)row0 * (2*HIDDEN) + hd * HEAD_DIM + (t << 1);
    __half* yp1 = yp0 + (size_t)8 * (2*HIDDEN);
    #pragma unroll
    for (int dn = 0; dn < 8; dn++) {
        *(uint32_t*)(yp0 + (dn << 3)) = pack_f16(o[dn][0] * il0, o[dn][1] * il0);
        *(uint32_t*)(yp1 + (dn << 3)) = pack_f16(o[dn][2] * il1, o[dn][3] * il1);
    }
}

// ---------------- mod GEMV: split-K partial + reduce ----------------------------
__global__ void __launch_bounds__(256) mod_partial(
        const float* __restrict__ vec, const float* __restrict__ w_mod,
        float* __restrict__ modp) {
    __shared__ float sv[128];
    const int b = blockIdx.z, ks = blockIdx.y;
    const int n = blockIdx.x * 256 + threadIdx.x;
    if (threadIdx.x < 128) {
        float v = vec[b * HIDDEN + ks * 128 + threadIdx.x];
        sv[threadIdx.x] = v / (1.0f + expf(-v));
    }
    __syncthreads();
    float acc = 0.0f;
    const float* W = w_mod + (size_t)(ks * 128) * (3 * HIDDEN) + n;
    #pragma unroll 8
    for (int k = 0; k < 128; k++)
        acc = fmaf(sv[k], W[(size_t)k * (3 * HIDDEN)], acc);
    modp[((ks * BB) + b) * (3 * HIDDEN) + n] = acc;
}

__global__ void __launch_bounds__(256) mod_reduce(
        const float* __restrict__ modp, const float* __restrict__ b_mod,
        float* __restrict__ mod) {
    const int idx = blockIdx.x * 256 + threadIdx.x;   // 0..BB*3072-1
    const int b = idx / (3 * HIDDEN), n = idx % (3 * HIDDEN);
    float s = b_mod[n];
    #pragma unroll
    for (int ks = 0; ks < 8; ks++)
        s += modp[((ks * BB) + b) * (3 * HIDDEN) + n];
    mod[idx] = s;
}

// ---------------- kernel 2: layernorm + modulate -> fp16 ------------------------
__global__ void __launch_bounds__(256) ln_mod_kernel(const float* __restrict__ x,
                                                     const float* __restrict__ mod,
                                                     __half* __restrict__ xmod) {
    __shared__ float sbuf[8];
    __shared__ float s_mean, s_rstd;
    int token = blockIdx.x;
    int b = token >> 11;
    int tid = threadIdx.x;
    const float4 xv = ((const float4*)(x + (size_t)token*HIDDEN))[tid];

    float s = xv.x + xv.y + xv.z + xv.w;
    #pragma unroll
    for (int o = 16; o > 0; o >>= 1) s += __shfl_xor_sync(0xffffffffu, s, o);
    if ((tid & 31) == 0) sbuf[tid >> 5] = s;
    __syncthreads();
    if (tid == 0) {
        float tq = 0;
        #pragma unroll
        for (int i = 0; i < 8; i++) tq += sbuf[i];
        s_mean = tq * (1.0f / HIDDEN);
    }
    __syncthreads();
    float m = s_mean;
    float dx = xv.x - m, dy = xv.y - m, dz = xv.z - m, dw = xv.w - m;
    float ss = dx*dx + dy*dy + dz*dz + dw*dw;
    #pragma unroll
    for (int o = 16; o > 0; o >>= 1) ss += __shfl_xor_sync(0xffffffffu, ss, o);
    __syncthreads();
    if ((tid & 31) == 0) sbuf[tid >> 5] = ss;
    __syncthreads();
    if (tid == 0) {
        float tq = 0;
        #pragma unroll
        for (int i = 0; i < 8; i++) tq += sbuf[i];
        s_rstd = rsqrtf(tq * (1.0f / HIDDEN) + 1e-6f);
    }
    __syncthreads();
    float r = s_rstd;
    int c = tid * 4;
    const float4 sh = *(const float4*)(mod + b*3*HIDDEN + c);
    const float4 sc = *(const float4*)(mod + b*3*HIDDEN + HIDDEN + c);
    float o0 = fmaf(1.0f + sc.x, dx*r, sh.x);
    float o1 = fmaf(1.0f + sc.y, dy*r, sh.y);
    float o2 = fmaf(1.0f + sc.z, dz*r, sh.z);
    float o3 = fmaf(1.0f + sc.w, dw*r, sh.w);
    uint32_t* dst = (uint32_t*)(xmod + (size_t)token*HIDDEN + c);
    dst[0] = pack_f16(o0, o1);
    dst[1] = pack_f16(o2, o3);
}

// ---------------- kernel 4: RMSNorm + RoPE, fp16 h -> per-head q/k/v ------------
__global__ void __launch_bounds__(512) qk_norm_rope_kernel(
        const __half* __restrict__ h,
        const float* __restrict__ pe,
        const float* __restrict__ q_scale,
        const float* __restrict__ k_scale,
        __half* __restrict__ qh, __half* __restrict__ kh, __half* __restrict__ vh) {
    int token = blockIdx.x;
    int l = token & (LL - 1);
    int b = token >> 11;
    int head = threadIdx.x >> 5;
    int lane = threadIdx.x & 31;

    const __half* hq = h + (size_t)token*W1N + head*HEAD_DIM;
    const size_t oidx = ((size_t)(b*HEADS + head)*LL + l)*HEAD_DIM + lane*2;

    const float4 p = *(const float4*)(pe + (size_t)l*128 + lane*4);
    float sx = q_scale[lane*2], sy = q_scale[lane*2+1];
    float kx = k_scale[lane*2], ky = k_scale[lane*2+1];

    {
        float2 q2 = __half22float2(*(const __half2*)(hq + lane*2));
        float ss = q2.x*q2.x + q2.y*q2.y;
        #pragma unroll
        for (int o = 16; o > 0; o >>= 1) ss += __shfl_xor_sync(0xffffffffu, ss, o);
        float rr = rsqrtf(ss * (1.0f/HEAD_DIM) + 1e-6f);
        float t0 = q2.x * rr * sx, t1 = q2.y * rr * sy;
        *(uint32_t*)(qh + oidx) =
            pack_f16(0.125f*(p.x*t0 + p.y*t1), 0.125f*(p.z*t0 + p.w*t1));
    }
    {
        float2 k2 = __half22float2(*(const __half2*)(hq + HIDDEN + lane*2));
        float ss = k2.x*k2.x + k2.y*k2.y;
        #pragma unroll
        for (int o = 16; o > 0; o >>= 1) ss += __shfl_xor_sync(0xffffffffu, ss, o);
        float rr = rsqrtf(ss * (1.0f/HEAD_DIM) + 1e-6f);
        float t0 = k2.x * rr * kx, t1 = k2.y * rr * ky;
        *(uint32_t*)(kh + oidx) = pack_f16(p.x*t0 + p.y*t1, p.z*t0 + p.w*t1);
    }
    *(__half2*)(vh + oidx) = *(const __half2*)(hq + 2*HIDDEN + lane*2);
}

// ---------------- launch --------------------------------------------------------
extern "C" void kernel_launch(void* const* d_in, const int* in_sizes, int n_in,
                              void* d_out, int out_size) {
    const float* x       = (const float*)d_in[0];
    const float* vec     = (const float*)d_in[1];
    const float* pe      = (const float*)d_in[2];
    const float* w_mod   = (const float*)d_in[3];
    const float* b_mod   = (const float*)d_in[4];
    const float* w1      = (const float*)d_in[5];
    const float* b1      = (const float*)d_in[6];
    const float* w_mlp   = (const float*)d_in[7];
    const float* b_mlp   = (const float*)d_in[8];
    const float* w2      = (const float*)d_in[9];
    const float* b2      = (const float*)d_in[10];
    const float* q_scale = (const float*)d_in[11];
    const float* k_scale = (const float*)d_in[12];
    float* out = (float*)d_out;

    float *mod, *modp;
    __half *xmod, *h, *qh, *kh, *vh, *y, *w1t, *wmlpt, *w2t;
    cudaGetSymbolAddress((void**)&mod,   g_mod);
    cudaGetSymbolAddress((void**)&modp,  g_modp);
    cudaGetSymbolAddress((void**)&xmod,  g_xmod);
    cudaGetSymbolAddress((void**)&h,     g_h);
    cudaGetSymbolAddress((void**)&qh,    g_qh);
    cudaGetSymbolAddress((void**)&kh,    g_kh);
    cudaGetSymbolAddress((void**)&vh,    g_vh);
    cudaGetSymbolAddress((void**)&y,     g_y);
    cudaGetSymbolAddress((void**)&w1t,   g_w1t);
    cudaGetSymbolAddress((void**)&wmlpt, g_wmlpt);
    cudaGetSymbolAddress((void**)&w2t,   g_w2t);

    cudaFuncSetAttribute(mma_gemm<0>, cudaFuncAttributeMaxDynamicSharedMemorySize, GEMM_SMEM);
    cudaFuncSetAttribute(mma_gemm<1>, cudaFuncAttributeMaxDynamicSharedMemorySize, GEMM_SMEM);
    cudaFuncSetAttribute(mma_gemm<2>, cudaFuncAttributeMaxDynamicSharedMemorySize, GEMM_SMEM);
    cudaFuncSetAttribute(attn_tc,     cudaFuncAttributeMaxDynamicSharedMemorySize, ATTN_SMEM);

    // 0. weight transposes -> fp16 [N][K]
    transpose_h<<<dim3(W1N/32,   HIDDEN/32),  dim3(32,8)>>>(w1,    w1t,   HIDDEN, W1N);
    transpose_h<<<dim3(HIDDEN/32, MLPH/32),   dim3(32,8)>>>(w_mlp, wmlpt, MLPH,   HIDDEN);
    transpose_h<<<dim3(HIDDEN/32, 2*HIDDEN/32), dim3(32,8)>>>(w2,  w2t,   2*HIDDEN, HIDDEN);
    // 1. modulation vector (split-K)
    mod_partial<<<dim3(3*HIDDEN/256, 8, BB), 256>>>(vec, w_mod, modp);
    mod_reduce<<<BB*3*HIDDEN/256, 256>>>(modp, b_mod, mod);
    // 2. layernorm + modulate -> fp16
    ln_mod_kernel<<<NTOK, 256>>>(x, mod, xmod);
    // 3. h = x_mod @ w1 + b1  -> fp16
    mma_gemm<0><<<dim3(W1N/128, NTOK/128), 256, GEMM_SMEM>>>(
        xmod, HIDDEN, w1t, HIDDEN, h, W1N, HIDDEN, b1, nullptr, nullptr);
    // 4. q,k rmsnorm + rope -> per-head fp16 buffers
    qk_norm_rope_kernel<<<NTOK, 512>>>(h, pe, q_scale, k_scale, qh, kh, vh);
    // 5. attention -> y[:, :1024] (fp16)
    attn_tc<<<dim3(LL/128, BB*HEADS), 256, ATTN_SMEM>>>(qh, kh, vh, y);
    // 6. y[:, 1024:] = tanh(mlp @ w_mlp + b_mlp) (fp16)
    mma_gemm<1><<<dim3(HIDDEN/128, NTOK/128), 256, GEMM_SMEM>>>(
        h + 3*HIDDEN, W1N, wmlpt, MLPH, y + HIDDEN, 2*HIDDEN,
        MLPH, b_mlp, nullptr, nullptr);
    // 7. out = x + gate * (y @ w2 + b2)  (fp32)
    mma_gemm<2><<<dim3(HIDDEN/128, NTOK/128), 256, GEMM_SMEM>>>(
        y, 2*HIDDEN, w2t, 2*HIDDEN, out, HIDDEN,
        2*HIDDEN, b2, x, mod);
}

// round 10
// speedup vs baseline: 9.9401x; 1.0966x over previous
#include <cuda_runtime.h>
#include <cuda_fp16.h>
#include <math.h>
#include <stdint.h>

#define HIDDEN   1024
#define HEADS    16
#define HEAD_DIM 64
#define MLPH     4096
#define BB       2
#define LL       2048
#define NTOK     (BB*LL)          // 4096
#define W1N      (3*HIDDEN+MLPH)  // 7168

// ---------------- scratch (static device globals; no runtime alloc) ------------
__device__ float  g_mod[BB*3*HIDDEN];                   // shift|scale|gate
__device__ float  g_modp[16*BB*3*HIDDEN];               // split-K partials
__device__ __half g_xmod[NTOK*HIDDEN];                  // fp16 LN output
__device__ __half g_h[(size_t)NTOK*W1N];                // fp16 qkv|mlp
__device__ __half g_qh[(size_t)BB*HEADS*LL*HEAD_DIM];   // roped q (pre-scaled)
__device__ __half g_kh[(size_t)BB*HEADS*LL*HEAD_DIM];   // roped k
__device__ __half g_vh[(size_t)BB*HEADS*LL*HEAD_DIM];   // v
__device__ __half g_y[(size_t)NTOK*2*HIDDEN];           // attn | tanh-mlp (fp16)
__device__ __half g_w1t[(size_t)W1N*HIDDEN];            // w1^T  [7168][1024]
__device__ __half g_wmlpt[(size_t)HIDDEN*MLPH];         // w_mlp^T [1024][4096]
__device__ __half g_w2t[(size_t)HIDDEN*2*HIDDEN];       // w2^T  [1024][2048]

// =================== helpers ====================================================
__device__ __forceinline__ uint32_t smem_u32(const void* p) {
    uint32_t a;
    asm("{ .reg .u64 t; cvta.to.shared.u64 t, %1; cvt.u32.u64 %0, t; }"
        : "=r"(a) : "l"(p));
    return a;
}
__device__ __forceinline__ uint32_t pack_f16(float lo, float hi) {
    uint32_t r;
    asm("cvt.rn.f16x2.f32 %0, %1, %2;" : "=r"(r) : "f"(hi), "f"(lo));
    return r;
}
__device__ __forceinline__ void mma_f16(float* c, const uint32_t* a, const uint32_t* b) {
    asm volatile(
        "mma.sync.aligned.m16n8k16.row.col.f32.f16.f16.f32 "
        "{%0,%1,%2,%3}, {%4,%5,%6,%7}, {%8,%9}, {%0,%1,%2,%3};"
        : "+f"(c[0]), "+f"(c[1]), "+f"(c[2]), "+f"(c[3])
        : "r"(a[0]), "r"(a[1]), "r"(a[2]), "r"(a[3]), "r"(b[0]), "r"(b[1]));
}
__device__ __forceinline__ void ldm_x4(uint32_t* r, uint32_t addr) {
    asm volatile("ldmatrix.sync.aligned.m8n8.x4.shared.b16 {%0,%1,%2,%3}, [%4];"
        : "=r"(r[0]), "=r"(r[1]), "=r"(r[2]), "=r"(r[3]) : "r"(addr));
}
__device__ __forceinline__ void ldm_x4_t(uint32_t* r, uint32_t addr) {
    asm volatile("ldmatrix.sync.aligned.m8n8.x4.trans.shared.b16 {%0,%1,%2,%3}, [%4];"
        : "=r"(r[0]), "=r"(r[1]), "=r"(r[2]), "=r"(r[3]) : "r"(addr));
}
__device__ __forceinline__ void cp16(uint32_t dst, const void* src) {
    asm volatile("cp.async.cg.shared.global [%0], [%1], 16;" :: "r"(dst), "l"(src));
}
__device__ __forceinline__ void cp_commit() {
    asm volatile("cp.async.commit_group;" ::: "memory");
}
template<int N>
__device__ __forceinline__ void cp_wait() {
    asm volatile("cp.async.wait_group %0;" :: "n"(N) : "memory");
}

// =================== transpose + convert: f32[K][N] -> f16[N][K] ================
__global__ void __launch_bounds__(256) transpose_h(
        const float* __restrict__ in, __half* __restrict__ out, int K, int N) {
    __shared__ float tile[32][33];
    const int n0 = blockIdx.x << 5, k0 = blockIdx.y << 5;
    const int tx = threadIdx.x, ty = threadIdx.y;
    #pragma unroll
    for (int i = 0; i < 4; i++)
        tile[ty + (i << 3)][tx] = in[(size_t)(k0 + ty + (i << 3)) * N + n0 + tx];
    __syncthreads();
    #pragma unroll
    for (int i = 0; i < 4; i++)
        out[(size_t)(n0 + ty + (i << 3)) * K + k0 + tx] =
            __float2half(tile[tx][ty + (i << 3)]);
}

// =================== fp16 GEMM: cp.async 3-stage, ldmatrix, mma m16n8k16 =======
static constexpr int PA = 40;                  // halves pitch (80 B)
static constexpr int TILE_B = 128 * PA * 2;    // 10240 B
static constexpr int STAGE_B = 2 * TILE_B;     // 20480 B
static constexpr uint32_t GEMM_SMEM = 3 * STAGE_B;   // 61440 B

__device__ __forceinline__ void gemm_issue(
        const __half* __restrict__ A, int lda,
        const __half* __restrict__ Bt, int ldb,
        int bm, int bn, int kt, int slot, uint32_t sbase, int tid) {
    const uint32_t dA = sbase + slot * STAGE_B;
    const __half* Ag = A + (size_t)bm * lda + (kt << 5);
    #pragma unroll
    for (int i = 0; i < 2; i++) {
        int idx = (i << 8) + tid;
        int r = idx >> 2, q = idx & 3;
        cp16(dA + r * 80 + (q << 4), Ag + (size_t)r * lda + (q << 3));
    }
    const uint32_t dB = dA + TILE_B;
    const __half* Bg = Bt + (size_t)bn * ldb + (kt << 5);
    #pragma unroll
    for (int i = 0; i < 2; i++) {
        int idx = (i << 8) + tid;
        int r = idx >> 2, q = idx & 3;
        cp16(dB + r * 80 + (q << 4), Bg + (size_t)r * ldb + (q << 3));
    }
    cp_commit();
}

template<int MODE>
__global__ void __launch_bounds__(256, 2) mma_gemm(
        const __half* __restrict__ A, int lda,
        const __half* __restrict__ Bt, int ldb,
        void* __restrict__ Cv, int ldc, int K,
        const float* __restrict__ bias,
        const float* __restrict__ xres,
        const float* __restrict__ mod) {
    extern __shared__ char smc[];
    const uint32_t sbase = smem_u32(smc);

    const int tid  = threadIdx.x;
    const int warp = tid >> 5;
    const int lane = tid & 31;
    const int g = lane >> 2, t = lane & 3;
    const int wm = (warp >> 2) * 64;
    const int wn = (warp & 3) * 32;
    const int bm = blockIdx.y << 7;
    const int bn = blockIdx.x << 7;

    const int rA = (lane & 7) + ((lane >> 3) & 1) * 8;
    const int cA = (lane >> 4) * 8;
    const int rB = (lane & 7) + (lane >> 4) * 8;
    const int cB = ((lane >> 3) & 1) * 8;
    const uint32_t aoff = ((wm + rA) * PA + cA) * 2;
    const uint32_t boff = ((wn + rB) * PA + cB) * 2;

    float acc[4][4][4];
    #pragma unroll
    for (int i = 0; i < 4; i++)
        #pragma unroll
        for (int j = 0; j < 4; j++)
            #pragma unroll
            for (int e = 0; e < 4; e++) acc[i][j][e] = 0.0f;

    const int NT = K >> 5;
    gemm_issue(A, lda, Bt, ldb, bm, bn, 0, 0, sbase, tid);
    gemm_issue(A, lda, Bt, ldb, bm, bn, 1, 1, sbase, tid);

    for (int kt = 0; kt < NT; kt++) {
        if (kt + 1 < NT) cp_wait<1>(); else cp_wait<0>();
        __syncthreads();
        if (kt + 2 < NT)
            gemm_issue(A, lda, Bt, ldb, bm, bn, kt + 2, (kt + 2) % 3, sbase, tid);

        const uint32_t sA_b = sbase + (kt % 3) * STAGE_B;
        const uint32_t sB_b = sA_b + TILE_B;
        #pragma unroll
        for (int kk = 0; kk < 2; kk++) {
            uint32_t af[4][4], bf[4][2];
            #pragma unroll
            for (int mt = 0; mt < 4; mt++)
                ldm_x4(af[mt], sA_b + aoff + ((mt * 16 * PA + kk * 16) << 1));
            #pragma unroll
            for (int ntp = 0; ntp < 2; ntp++) {
                uint32_t tmp[4];
                ldm_x4(tmp, sB_b + boff + ((ntp * 16 * PA + kk * 16) << 1));
                bf[2*ntp][0]   = tmp[0]; bf[2*ntp][1]   = tmp[1];
                bf[2*ntp+1][0] = tmp[2]; bf[2*ntp+1][1] = tmp[3];
            }
            #pragma unroll
            for (int mt = 0; mt < 4; mt++)
                #pragma unroll
                for (int nt = 0; nt < 4; nt++)
                    mma_f16(acc[mt][nt], af[mt], bf[nt]);
        }
    }

    // ---- epilogue ----
    #pragma unroll
    for (int nt = 0; nt < 4; nt++) {
        const int col = bn + wn + (nt << 3) + (t << 1);
        const float2 bi = *(const float2*)(bias + col);
        #pragma unroll
        for (int mt = 0; mt < 4; mt++) {
            const int r0 = bm + wm + (mt << 4) + g;
            float2 v0, v1;
            v0.x = acc[mt][nt][0] + bi.x;  v0.y = acc[mt][nt][1] + bi.y;
            v1.x = acc[mt][nt][2] + bi.x;  v1.y = acc[mt][nt][3] + bi.y;
            if (MODE == 1) {
                v0.x = tanhf(v0.x); v0.y = tanhf(v0.y);
                v1.x = tanhf(v1.x); v1.y = tanhf(v1.y);
            }
            if (MODE == 2) {
                float* C = (float*)Cv;
                const int b0 = r0 >> 11;
                const float2 g2 = *(const float2*)(mod + b0*3*HIDDEN + 2*HIDDEN + col);
                const float2 x0 = *(const float2*)(xres + (size_t)r0*HIDDEN + col);
                const float2 x1 = *(const float2*)(xres + (size_t)(r0+8)*HIDDEN + col);
                v0.x = fmaf(g2.x, v0.x, x0.x); v0.y = fmaf(g2.y, v0.y, x0.y);
                v1.x = fmaf(g2.x, v1.x, x1.x); v1.y = fmaf(g2.y, v1.y, x1.y);
                *(float2*)(C + (size_t)r0 * ldc + col)       = v0;
                *(float2*)(C + (size_t)(r0 + 8) * ldc + col) = v1;
            } else {
                __half* C = (__half*)Cv;
                *(uint32_t*)(C + (size_t)r0 * ldc + col)       = pack_f16(v0.x, v0.y);
                *(uint32_t*)(C + (size_t)(r0 + 8) * ldc + col) = pack_f16(v1.x, v1.y);
            }
        }
    }
}

// =================== fp16 flash attention (ldmatrix frags) ======================
static constexpr int PQ = 72;                        // halves pitch (144 B)
static constexpr int Q_BYTES  = 128 * PQ * 2;        // 18432
static constexpr int KV_BYTES = 64 * PQ * 2;         // 9216
static constexpr uint32_t ATTN_SMEM = Q_BYTES + 4 * KV_BYTES;  // 55296

__device__ __forceinline__ void attn_issue_kv(
        const __half* __restrict__ kh, const __half* __restrict__ vh,
        int kt, int slot, uint32_t sbase, int tid) {
    #pragma unroll
    for (int i = 0; i < 2; i++) {
        const int idx = (i << 8) + tid;
        const int r = idx >> 3, q = idx & 7;
        const int row = (kt << 6) + r;
        const uint32_t dK = sbase + Q_BYTES + slot * KV_BYTES + r * 144 + (q << 4);
        cp16(dK,                kh + (size_t)row * 64 + (q << 3));
        cp16(dK + 2 * KV_BYTES, vh + (size_t)row * 64 + (q << 3));
    }
    cp_commit();
}

__global__ void __launch_bounds__(256, 2) attn_tc(
        const __half* __restrict__ qh, const __half* __restrict__ kh,
        const __half* __restrict__ vh, __half* __restrict__ y) {
    extern __shared__ char smc[];
    __half* const smh = (__half*)smc;
    const uint32_t sbase = smem_u32(smc);

    const int tid  = threadIdx.x;
    const int warp = tid >> 5;
    const int lane = tid & 31;
    const int g = lane >> 2, t = lane & 3;
    const int bh = blockIdx.y;
    const int q0 = blockIdx.x << 7;

    const __half* qb = qh + (size_t)bh * LL * HEAD_DIM;
    const __half* kb = kh + (size_t)bh * LL * HEAD_DIM;
    const __half* vb = vh + (size_t)bh * LL * HEAD_DIM;

    const int rK = (lane & 7) + (lane >> 4) * 8;
    const int cK = ((lane >> 3) & 1) * 8;
    const int rV = (lane & 7) + ((lane >> 3) & 1) * 8;
    const int cV = (lane >> 4) * 8;
    const uint32_t koff = (rK * PQ + cK) * 2;
    const uint32_t voff = (rV * PQ + cV) * 2;

    #pragma unroll
    for (int i = 0; i < 4; i++) {
        int idx = (i << 8) + tid;
        int r = idx >> 3, q = idx & 7;
        *(uint4*)(smh + r * PQ + (q << 3)) =
            *(const uint4*)(qb + (size_t)(q0 + r) * 64 + (q << 3));
    }
    __syncthreads();
    uint32_t qa[4][4];
    {
        const uint32_t qoff = (((warp << 4) + rV) * PQ + cV) * 2;
        #pragma unroll
        for (int kk = 0; kk < 4; kk++)
            ldm_x4(qa[kk], sbase + qoff + ((kk * 16) << 1));
    }
    __syncthreads();

    float o[8][4];
    #pragma unroll
    for (int dn = 0; dn < 8; dn++)
        #pragma unroll
        for (int e = 0; e < 4; e++) o[dn][e] = 0.0f;
    float m0 = -1e30f, m1 = -1e30f, l0 = 0.0f, l1 = 0.0f;

    attn_issue_kv(kb, vb, 0, 0, sbase, tid);

    const int NT = LL / 64;
    for (int kt = 0; kt < NT; kt++) {
        cp_wait<0>();
        __syncthreads();
        if (kt + 1 < NT)
            attn_issue_kv(kb, vb, kt + 1, (kt + 1) & 1, sbase, tid);

        const uint32_t sK_b = sbase + Q_BYTES + (kt & 1) * KV_BYTES;
        const uint32_t sV_b = sK_b + 2 * KV_BYTES;

        float s[8][4];
        #pragma unroll
        for (int nt = 0; nt < 8; nt++)
            #pragma unroll
            for (int e = 0; e < 4; e++) s[nt][e] = 0.0f;
        #pragma unroll
        for (int kk = 0; kk < 4; kk++) {
            uint32_t kf[8][2];
            #pragma unroll
            for (int ntp = 0; ntp < 4; ntp++) {
                uint32_t tmp[4];
                ldm_x4(tmp, sK_b + koff + ((ntp * 16 * PQ + kk * 16) << 1));
                kf[2*ntp][0]   = tmp[0]; kf[2*ntp][1]   = tmp[1];
                kf[2*ntp+1][0] = tmp[2]; kf[2*ntp+1][1] = tmp[3];
            }
            #pragma unroll
            for (int nt = 0; nt < 8; nt++)
                mma_f16(s[nt], qa[kk], kf[nt]);
        }

        float mx0 = -1e30f, mx1 = -1e30f;
        #pragma unroll
        for (int nt = 0; nt < 8; nt++) {
            mx0 = fmaxf(mx0, fmaxf(s[nt][0], s[nt][1]));
            mx1 = fmaxf(mx1, fmaxf(s[nt][2], s[nt][3]));
        }
        mx0 = fmaxf(mx0, __shfl_xor_sync(0xffffffffu, mx0, 1));
        mx0 = fmaxf(mx0, __shfl_xor_sync(0xffffffffu, mx0, 2));
        mx1 = fmaxf(mx1, __shfl_xor_sync(0xffffffffu, mx1, 1));
        mx1 = fmaxf(mx1, __shfl_xor_sync(0xffffffffu, mx1, 2));
        const float M0 = fmaxf(m0, mx0), M1 = fmaxf(m1, mx1);
        const float f0 = __expf(m0 - M0), f1 = __expf(m1 - M1);
        m0 = M0; m1 = M1;

        float sum0 = 0.0f, sum1 = 0.0f;
        #pragma unroll
        for (int nt = 0; nt < 8; nt++) {
            s[nt][0] = __expf(s[nt][0] - M0);
            s[nt][1] = __expf(s[nt][1] - M0);
            s[nt][2] = __expf(s[nt][2] - M1);
            s[nt][3] = __expf(s[nt][3] - M1);
            sum0 += s[nt][0] + s[nt][1];
            sum1 += s[nt][2] + s[nt][3];
        }
        sum0 += __shfl_xor_sync(0xffffffffu, sum0, 1);
        sum0 += __shfl_xor_sync(0xffffffffu, sum0, 2);
        sum1 += __shfl_xor_sync(0xffffffffu, sum1, 1);
        sum1 += __shfl_xor_sync(0xffffffffu, sum1, 2);
        l0 = l0 * f0 + sum0;
        l1 = l1 * f1 + sum1;

        #pragma unroll
        for (int dn = 0; dn < 8; dn++) {
            o[dn][0] *= f0; o[dn][1] *= f0;
            o[dn][2] *= f1; o[dn][3] *= f1;
        }

        uint32_t pa[4][4];
        #pragma unroll
        for (int kc = 0; kc < 4; kc++) {
            pa[kc][0] = pack_f16(s[2*kc][0],   s[2*kc][1]);
            pa[kc][1] = pack_f16(s[2*kc][2],   s[2*kc][3]);
            pa[kc][2] = pack_f16(s[2*kc+1][0], s[2*kc+1][1]);
            pa[kc][3] = pack_f16(s[2*kc+1][2], s[2*kc+1][3]);
        }

        #pragma unroll
        for (int kc = 0; kc < 4; kc++) {
            #pragma unroll
            for (int dnp = 0; dnp < 4; dnp++) {
                uint32_t tmp[4];
                ldm_x4_t(tmp, sV_b + voff + ((kc * 16 * PQ + dnp * 16) << 1));
                mma_f16(o[2*dnp],   pa[kc], tmp);
                mma_f16(o[2*dnp+1], pa[kc], tmp + 2);
            }
        }
        __syncthreads();
    }

    const float il0 = 1.0f / l0, il1 = 1.0f / l1;
    const int hd = bh & 15;
    const int row0 = (bh >> 4) * LL + q0 + (warp << 4) + g;
    __half* yp0 = y + (size_t)row0 * (2*HIDDEN) + hd * HEAD_DIM + (t << 1);
    __half* yp1 = yp0 + (size_t)8 * (2*HIDDEN);
    #pragma unroll
    for (int dn = 0; dn < 8; dn++) {
        *(uint32_t*)(yp0 + (dn << 3)) = pack_f16(o[dn][0] * il0, o[dn][1] * il0);
        *(uint32_t*)(yp1 + (dn << 3)) = pack_f16(o[dn][2] * il1, o[dn][3] * il1);
    }
}

// ---------------- mod GEMV: split-K(16) partial + reduce ------------------------
__global__ void __launch_bounds__(256) mod_partial(
        const float* __restrict__ vec, const float* __restrict__ w_mod,
        float* __restrict__ modp) {
    __shared__ float sv[64];
    const int b = blockIdx.z, ks = blockIdx.y;          // ks 0..15
    const int n = blockIdx.x * 256 + threadIdx.x;
    if (threadIdx.x < 64) {
        float v = vec[b * HIDDEN + ks * 64 + threadIdx.x];
        sv[threadIdx.x] = v / (1.0f + expf(-v));
    }
    __syncthreads();
    float acc = 0.0f;
    const float* W = w_mod + (size_t)(ks * 64) * (3 * HIDDEN) + n;
    #pragma unroll 8
    for (int k = 0; k < 64; k++)
        acc = fmaf(sv[k], W[(size_t)k * (3 * HIDDEN)], acc);
    modp[((ks * BB) + b) * (3 * HIDDEN) + n] = acc;
}

__global__ void __launch_bounds__(256) mod_reduce(
        const float* __restrict__ modp, const float* __restrict__ b_mod,
        float* __restrict__ mod) {
    const int idx = blockIdx.x * 256 + threadIdx.x;
    const int b = idx / (3 * HIDDEN), n = idx % (3 * HIDDEN);
    float s = b_mod[n];
    #pragma unroll
    for (int ks = 0; ks < 16; ks++)
        s += modp[((ks * BB) + b) * (3 * HIDDEN) + n];
    mod[idx] = s;
}

// ---------------- kernel 2: layernorm + modulate -> fp16 ------------------------
__global__ void __launch_bounds__(256) ln_mod_kernel(const float* __restrict__ x,
                                                     const float* __restrict__ mod,
                                                     __half* __restrict__ xmod) {
    __shared__ float sbuf[8];
    __shared__ float s_mean, s_rstd;
    int token = blockIdx.x;
    int b = token >> 11;
    int tid = threadIdx.x;
    const float4 xv = ((const float4*)(x + (size_t)token*HIDDEN))[tid];

    float s = xv.x + xv.y + xv.z + xv.w;
    #pragma unroll
    for (int o = 16; o > 0; o >>= 1) s += __shfl_xor_sync(0xffffffffu, s, o);
    if ((tid & 31) == 0) sbuf[tid >> 5] = s;
    __syncthreads();
    if (tid == 0) {
        float tq = 0;
        #pragma unroll
        for (int i = 0; i < 8; i++) tq += sbuf[i];
        s_mean = tq * (1.0f / HIDDEN);
    }
    __syncthreads();
    float m = s_mean;
    float dx = xv.x - m, dy = xv.y - m, dz = xv.z - m, dw = xv.w - m;
    float ss = dx*dx + dy*dy + dz*dz + dw*dw;
    #pragma unroll
    for (int o = 16; o > 0; o >>= 1) ss += __shfl_xor_sync(0xffffffffu, ss, o);
    __syncthreads();
    if ((tid & 31) == 0) sbuf[tid >> 5] = ss;
    __syncthreads();
    if (tid == 0) {
        float tq = 0;
        #pragma unroll
        for (int i = 0; i < 8; i++) tq += sbuf[i];
        s_rstd = rsqrtf(tq * (1.0f / HIDDEN) + 1e-6f);
    }
    __syncthreads();
    float r = s_rstd;
    int c = tid * 4;
    const float4 sh = *(const float4*)(mod + b*3*HIDDEN + c);
    const float4 sc = *(const float4*)(mod + b*3*HIDDEN + HIDDEN + c);
    float o0 = fmaf(1.0f + sc.x, dx*r, sh.x);
    float o1 = fmaf(1.0f + sc.y, dy*r, sh.y);
    float o2 = fmaf(1.0f + sc.z, dz*r, sh.z);
    float o3 = fmaf(1.0f + sc.w, dw*r, sh.w);
    uint32_t* dst = (uint32_t*)(xmod + (size_t)token*HIDDEN + c);
    dst[0] = pack_f16(o0, o1);
    dst[1] = pack_f16(o2, o3);
}

// ---------------- kernel 4: RMSNorm + RoPE, fp16 h -> per-head q/k/v ------------
__global__ void __launch_bounds__(512) qk_norm_rope_kernel(
        const __half* __restrict__ h,
        const float* __restrict__ pe,
        const float* __restrict__ q_scale,
        const float* __restrict__ k_scale,
        __half* __restrict__ qh, __half* __restrict__ kh, __half* __restrict__ vh) {
    int token = blockIdx.x;
    int l = token & (LL - 1);
    int b = token >> 11;
    int head = threadIdx.x >> 5;
    int lane = threadIdx.x & 31;

    const __half* hq = h + (size_t)token*W1N + head*HEAD_DIM;
    const size_t oidx = ((size_t)(b*HEADS + head)*LL + l)*HEAD_DIM + lane*2;

    const float4 p = *(const float4*)(pe + (size_t)l*128 + lane*4);
    float sx = q_scale[lane*2], sy = q_scale[lane*2+1];
    float kx = k_scale[lane*2], ky = k_scale[lane*2+1];

    {
        float2 q2 = __half22float2(*(const __half2*)(hq + lane*2));
        float ss = q2.x*q2.x + q2.y*q2.y;
        #pragma unroll
        for (int o = 16; o > 0; o >>= 1) ss += __shfl_xor_sync(0xffffffffu, ss, o);
        float rr = rsqrtf(ss * (1.0f/HEAD_DIM) + 1e-6f);
        float t0 = q2.x * rr * sx, t1 = q2.y * rr * sy;
        *(uint32_t*)(qh + oidx) =
            pack_f16(0.125f*(p.x*t0 + p.y*t1), 0.125f*(p.z*t0 + p.w*t1));
    }
    {
        float2 k2 = __half22float2(*(const __half2*)(hq + HIDDEN + lane*2));
        float ss = k2.x*k2.x + k2.y*k2.y;
        #pragma unroll
        for (int o = 16; o > 0; o >>= 1) ss += __shfl_xor_sync(0xffffffffu, ss, o);
        float rr = rsqrtf(ss * (1.0f/HEAD_DIM) + 1e-6f);
        float t0 = k2.x * rr * kx, t1 = k2.y * rr * ky;
        *(uint32_t*)(kh + oidx) = pack_f16(p.x*t0 + p.y*t1, p.z*t0 + p.w*t1);
    }
    *(__half2*)(vh + oidx) = *(const __half2*)(hq + 2*HIDDEN + lane*2);
}

// ---------------- launch --------------------------------------------------------
extern "C" void kernel_launch(void* const* d_in, const int* in_sizes, int n_in,
                              void* d_out, int out_size) {
    const float* x       = (const float*)d_in[0];
    const float* vec     = (const float*)d_in[1];
    const float* pe      = (const float*)d_in[2];
    const float* w_mod   = (const float*)d_in[3];
    const float* b_mod   = (const float*)d_in[4];
    const float* w1      = (const float*)d_in[5];
    const float* b1      = (const float*)d_in[6];
    const float* w_mlp   = (const float*)d_in[7];
    const float* b_mlp   = (const float*)d_in[8];
    const float* w2      = (const float*)d_in[9];
    const float* b2      = (const float*)d_in[10];
    const float* q_scale = (const float*)d_in[11];
    const float* k_scale = (const float*)d_in[12];
    float* out = (float*)d_out;

    float *mod, *modp;
    __half *xmod, *h, *qh, *kh, *vh, *y, *w1t, *wmlpt, *w2t;
    cudaGetSymbolAddress((void**)&mod,   g_mod);
    cudaGetSymbolAddress((void**)&modp,  g_modp);
    cudaGetSymbolAddress((void**)&xmod,  g_xmod);
    cudaGetSymbolAddress((void**)&h,     g_h);
    cudaGetSymbolAddress((void**)&qh,    g_qh);
    cudaGetSymbolAddress((void**)&kh,    g_kh);
    cudaGetSymbolAddress((void**)&vh,    g_vh);
    cudaGetSymbolAddress((void**)&y,     g_y);
    cudaGetSymbolAddress((void**)&w1t,   g_w1t);
    cudaGetSymbolAddress((void**)&wmlpt, g_wmlpt);
    cudaGetSymbolAddress((void**)&w2t,   g_w2t);

    static cudaStream_t s1 = nullptr;
    static cudaEvent_t evF = nullptr, evW1 = nullptr, evH = nullptr, evMLP = nullptr;
    if (!s1) {
        cudaStreamCreateWithFlags(&s1, cudaStreamNonBlocking);
        cudaEventCreateWithFlags(&evF,   cudaEventDisableTiming);
        cudaEventCreateWithFlags(&evW1,  cudaEventDisableTiming);
        cudaEventCreateWithFlags(&evH,   cudaEventDisableTiming);
        cudaEventCreateWithFlags(&evMLP, cudaEventDisableTiming);
        cudaFuncSetAttribute(mma_gemm<0>, cudaFuncAttributeMaxDynamicSharedMemorySize, GEMM_SMEM);
        cudaFuncSetAttribute(mma_gemm<1>, cudaFuncAttributeMaxDynamicSharedMemorySize, GEMM_SMEM);
        cudaFuncSetAttribute(mma_gemm<2>, cudaFuncAttributeMaxDynamicSharedMemorySize, GEMM_SMEM);
        cudaFuncSetAttribute(attn_tc,     cudaFuncAttributeMaxDynamicSharedMemorySize, ATTN_SMEM);
    }

    // fork side stream from main (legacy) stream
    cudaEventRecord(evF, 0);
    cudaStreamWaitEvent(s1, evF, 0);

    // side: weight transposes (w1t first; it gates GEMM0)
    transpose_h<<<dim3(W1N/32, HIDDEN/32), dim3(32,8), 0, s1>>>(w1, w1t, HIDDEN, W1N);
    cudaEventRecord(evW1, s1);
    transpose_h<<<dim3(HIDDEN/32, MLPH/32),     dim3(32,8), 0, s1>>>(w_mlp, wmlpt, MLPH,     HIDDEN);
    transpose_h<<<dim3(HIDDEN/32, 2*HIDDEN/32), dim3(32,8), 0, s1>>>(w2,    w2t,   2*HIDDEN, HIDDEN);

    // main: modulation + layernorm (concurrent with transposes)
    mod_partial<<<dim3(3*HIDDEN/256, 16, BB), 256>>>(vec, w_mod, modp);
    mod_reduce<<<BB*3*HIDDEN/256, 256>>>(modp, b_mod, mod);
    ln_mod_kernel<<<NTOK, 256>>>(x, mod, xmod);

    // main: GEMM0 (needs xmod + w1t)
    cudaStreamWaitEvent(0, evW1, 0);
    mma_gemm<0><<<dim3(W1N/128, NTOK/128), 256, GEMM_SMEM>>>(
        xmod, HIDDEN, w1t, HIDDEN, h, W1N, HIDDEN, b1, nullptr, nullptr);
    cudaEventRecord(evH, 0);

    // side: MLP GEMM (needs h + wmlpt), overlaps rope+attn on main
    cudaStreamWaitEvent(s1, evH, 0);
    mma_gemm<1><<<dim3(HIDDEN/128, NTOK/128), 256, GEMM_SMEM, s1>>>(
        h + 3*HIDDEN, W1N, wmlpt, MLPH, y + HIDDEN, 2*HIDDEN,
        MLPH, b_mlp, nullptr, nullptr);
    cudaEventRecord(evMLP, s1);

    // main: rope + attention
    qk_norm_rope_kernel<<<NTOK, 512>>>(h, pe, q_scale, k_scale, qh, kh, vh);
    attn_tc<<<dim3(LL/128, BB*HEADS), 256, ATTN_SMEM>>>(qh, kh, vh, y);

    // join, final GEMM
    cudaStreamWaitEvent(0, evMLP, 0);
    mma_gemm<2><<<dim3(HIDDEN/128, NTOK/128), 256, GEMM_SMEM>>>(
        y, 2*HIDDEN, w2t, 2*HIDDEN, out, HIDDEN,
        2*HIDDEN, b2, x, mod);
}

// round 11
// speedup vs baseline: 9.9725x; 1.0033x over previous
#include <cuda_runtime.h>
#include <cuda_fp16.h>
#include <math.h>
#include <stdint.h>

#define HIDDEN   1024
#define HEADS    16
#define HEAD_DIM 64
#define MLPH     4096
#define BB       2
#define LL       2048
#define NTOK     (BB*LL)          // 4096
#define W1N      (3*HIDDEN+MLPH)  // 7168

// ---------------- scratch (static device globals; no runtime alloc) ------------
__device__ float  g_mod[BB*3*HIDDEN];                   // shift|scale|gate
__device__ float  g_modp[16*BB*3*HIDDEN];               // split-K partials
__device__ __half g_xmod[NTOK*HIDDEN];                  // fp16 LN output
__device__ __half g_h[(size_t)NTOK*W1N];                // fp16 qkv|mlp
__device__ __half g_qh[(size_t)BB*HEADS*LL*HEAD_DIM];   // roped q (pre-scaled)
__device__ __half g_kh[(size_t)BB*HEADS*LL*HEAD_DIM];   // roped k
__device__ __half g_y[(size_t)NTOK*2*HIDDEN];           // attn | tanh-mlp (fp16)
__device__ __half g_w1t[(size_t)W1N*HIDDEN];            // w1^T  [7168][1024]
__device__ __half g_wmlpt[(size_t)HIDDEN*MLPH];         // w_mlp^T [1024][4096]
__device__ __half g_w2t[(size_t)HIDDEN*2*HIDDEN];       // w2^T  [1024][2048]

// =================== helpers ====================================================
__device__ __forceinline__ uint32_t smem_u32(const void* p) {
    uint32_t a;
    asm("{ .reg .u64 t; cvta.to.shared.u64 t, %1; cvt.u32.u64 %0, t; }"
        : "=r"(a) : "l"(p));
    return a;
}
__device__ __forceinline__ uint32_t pack_f16(float lo, float hi) {
    uint32_t r;
    asm("cvt.rn.f16x2.f32 %0, %1, %2;" : "=r"(r) : "f"(hi), "f"(lo));
    return r;
}
__device__ __forceinline__ void mma_f16(float* c, const uint32_t* a, const uint32_t* b) {
    asm volatile(
        "mma.sync.aligned.m16n8k16.row.col.f32.f16.f16.f32 "
        "{%0,%1,%2,%3}, {%4,%5,%6,%7}, {%8,%9}, {%0,%1,%2,%3};"
        : "+f"(c[0]), "+f"(c[1]), "+f"(c[2]), "+f"(c[3])
        : "r"(a[0]), "r"(a[1]), "r"(a[2]), "r"(a[3]), "r"(b[0]), "r"(b[1]));
}
__device__ __forceinline__ void ldm_x4(uint32_t* r, uint32_t addr) {
    asm volatile("ldmatrix.sync.aligned.m8n8.x4.shared.b16 {%0,%1,%2,%3}, [%4];"
        : "=r"(r[0]), "=r"(r[1]), "=r"(r[2]), "=r"(r[3]) : "r"(addr));
}
__device__ __forceinline__ void ldm_x4_t(uint32_t* r, uint32_t addr) {
    asm volatile("ldmatrix.sync.aligned.m8n8.x4.trans.shared.b16 {%0,%1,%2,%3}, [%4];"
        : "=r"(r[0]), "=r"(r[1]), "=r"(r[2]), "=r"(r[3]) : "r"(addr));
}
__device__ __forceinline__ void cp16(uint32_t dst, const void* src) {
    asm volatile("cp.async.cg.shared.global [%0], [%1], 16;" :: "r"(dst), "l"(src));
}
__device__ __forceinline__ void cp_commit() {
    asm volatile("cp.async.commit_group;" ::: "memory");
}
template<int N>
__device__ __forceinline__ void cp_wait() {
    asm volatile("cp.async.wait_group %0;" :: "n"(N) : "memory");
}

// =================== transpose + convert: f32[K][N] -> f16[N][K] ================
__global__ void __launch_bounds__(256) transpose_h(
        const float* __restrict__ in, __half* __restrict__ out, int K, int N) {
    __shared__ float tile[32][33];
    const int n0 = blockIdx.x << 5, k0 = blockIdx.y << 5;
    const int tx = threadIdx.x, ty = threadIdx.y;
    #pragma unroll
    for (int i = 0; i < 4; i++)
        tile[ty + (i << 3)][tx] = in[(size_t)(k0 + ty + (i << 3)) * N + n0 + tx];
    __syncthreads();
    #pragma unroll
    for (int i = 0; i < 4; i++)
        out[(size_t)(n0 + ty + (i << 3)) * K + k0 + tx] =
            __float2half(tile[tx][ty + (i << 3)]);
}

// =================== fp16 GEMM: cp.async 4-stage, ldmatrix, mma m16n8k16 =======
static constexpr int PA = 40;                  // halves pitch (80 B)
static constexpr int TILE_B = 128 * PA * 2;    // 10240 B
static constexpr int STAGE_B = 2 * TILE_B;     // 20480 B
static constexpr uint32_t GEMM_SMEM = 4 * STAGE_B;   // 81920 B

__device__ __forceinline__ void gemm_issue(
        const __half* __restrict__ A, int lda,
        const __half* __restrict__ Bt, int ldb,
        int bm, int bn, int kt, int slot, uint32_t sbase, int tid) {
    const uint32_t dA = sbase + slot * STAGE_B;
    const __half* Ag = A + (size_t)bm * lda + (kt << 5);
    #pragma unroll
    for (int i = 0; i < 2; i++) {
        int idx = (i << 8) + tid;
        int r = idx >> 2, q = idx & 3;
        cp16(dA + r * 80 + (q << 4), Ag + (size_t)r * lda + (q << 3));
    }
    const uint32_t dB = dA + TILE_B;
    const __half* Bg = Bt + (size_t)bn * ldb + (kt << 5);
    #pragma unroll
    for (int i = 0; i < 2; i++) {
        int idx = (i << 8) + tid;
        int r = idx >> 2, q = idx & 3;
        cp16(dB + r * 80 + (q << 4), Bg + (size_t)r * ldb + (q << 3));
    }
    cp_commit();
}

template<int MODE>
__global__ void __launch_bounds__(256, 2) mma_gemm(
        const __half* __restrict__ A, int lda,
        const __half* __restrict__ Bt, int ldb,
        void* __restrict__ Cv, int ldc, int K,
        const float* __restrict__ bias,
        const float* __restrict__ xres,
        const float* __restrict__ mod) {
    extern __shared__ char smc[];
    const uint32_t sbase = smem_u32(smc);

    const int tid  = threadIdx.x;
    const int warp = tid >> 5;
    const int lane = tid & 31;
    const int g = lane >> 2, t = lane & 3;
    const int wm = (warp >> 2) * 64;
    const int wn = (warp & 3) * 32;
    const int bm = blockIdx.y << 7;
    const int bn = blockIdx.x << 7;

    const int rA = (lane & 7) + ((lane >> 3) & 1) * 8;
    const int cA = (lane >> 4) * 8;
    const int rB = (lane & 7) + (lane >> 4) * 8;
    const int cB = ((lane >> 3) & 1) * 8;
    const uint32_t aoff = ((wm + rA) * PA + cA) * 2;
    const uint32_t boff = ((wn + rB) * PA + cB) * 2;

    float acc[4][4][4];
    #pragma unroll
    for (int i = 0; i < 4; i++)
        #pragma unroll
        for (int j = 0; j < 4; j++)
            #pragma unroll
            for (int e = 0; e < 4; e++) acc[i][j][e] = 0.0f;

    const int NT = K >> 5;
    gemm_issue(A, lda, Bt, ldb, bm, bn, 0, 0, sbase, tid);
    gemm_issue(A, lda, Bt, ldb, bm, bn, 1, 1, sbase, tid);
    gemm_issue(A, lda, Bt, ldb, bm, bn, 2, 2, sbase, tid);

    for (int kt = 0; kt < NT; kt++) {
        if (kt + 2 < NT)      cp_wait<2>();
        else if (kt + 1 < NT) cp_wait<1>();
        else                  cp_wait<0>();
        __syncthreads();
        if (kt + 3 < NT)
            gemm_issue(A, lda, Bt, ldb, bm, bn, kt + 3, (kt + 3) & 3, sbase, tid);

        const uint32_t sA_b = sbase + (kt & 3) * STAGE_B;
        const uint32_t sB_b = sA_b + TILE_B;
        #pragma unroll
        for (int kk = 0; kk < 2; kk++) {
            uint32_t af[4][4], bf[4][2];
            #pragma unroll
            for (int mt = 0; mt < 4; mt++)
                ldm_x4(af[mt], sA_b + aoff + ((mt * 16 * PA + kk * 16) << 1));
            #pragma unroll
            for (int ntp = 0; ntp < 2; ntp++) {
                uint32_t tmp[4];
                ldm_x4(tmp, sB_b + boff + ((ntp * 16 * PA + kk * 16) << 1));
                bf[2*ntp][0]   = tmp[0]; bf[2*ntp][1]   = tmp[1];
                bf[2*ntp+1][0] = tmp[2]; bf[2*ntp+1][1] = tmp[3];
            }
            #pragma unroll
            for (int mt = 0; mt < 4; mt++)
                #pragma unroll
                for (int nt = 0; nt < 4; nt++)
                    mma_f16(acc[mt][nt], af[mt], bf[nt]);
        }
    }

    // ---- epilogue ----
    #pragma unroll
    for (int nt = 0; nt < 4; nt++) {
        const int col = bn + wn + (nt << 3) + (t << 1);
        const float2 bi = *(const float2*)(bias + col);
        #pragma unroll
        for (int mt = 0; mt < 4; mt++) {
            const int r0 = bm + wm + (mt << 4) + g;
            float2 v0, v1;
            v0.x = acc[mt][nt][0] + bi.x;  v0.y = acc[mt][nt][1] + bi.y;
            v1.x = acc[mt][nt][2] + bi.x;  v1.y = acc[mt][nt][3] + bi.y;
            if (MODE == 1) {
                v0.x = tanhf(v0.x); v0.y = tanhf(v0.y);
                v1.x = tanhf(v1.x); v1.y = tanhf(v1.y);
            }
            if (MODE == 2) {
                float* C = (float*)Cv;
                const int b0 = r0 >> 11;
                const float2 g2 = *(const float2*)(mod + b0*3*HIDDEN + 2*HIDDEN + col);
                const float2 x0 = *(const float2*)(xres + (size_t)r0*HIDDEN + col);
                const float2 x1 = *(const float2*)(xres + (size_t)(r0+8)*HIDDEN + col);
                v0.x = fmaf(g2.x, v0.x, x0.x); v0.y = fmaf(g2.y, v0.y, x0.y);
                v1.x = fmaf(g2.x, v1.x, x1.x); v1.y = fmaf(g2.y, v1.y, x1.y);
                *(float2*)(C + (size_t)r0 * ldc + col)       = v0;
                *(float2*)(C + (size_t)(r0 + 8) * ldc + col) = v1;
            } else {
                __half* C = (__half*)Cv;
                *(uint32_t*)(C + (size_t)r0 * ldc + col)       = pack_f16(v0.x, v0.y);
                *(uint32_t*)(C + (size_t)(r0 + 8) * ldc + col) = pack_f16(v1.x, v1.y);
            }
        }
    }
}

// =================== fp16 flash attention (3-slot KV ring) =====================
static constexpr int PQ = 72;                        // halves pitch (144 B)
static constexpr int Q_BYTES  = 128 * PQ * 2;        // 18432
static constexpr int KV_SLOT  = 64 * PQ * 2;         // 9216
static constexpr uint32_t ATTN_SMEM = Q_BYTES + 6 * KV_SLOT;  // 73728

// K from packed per-head buffer; V strided directly from g_h (rows 128B contiguous)
__device__ __forceinline__ void attn_issue_kv(
        const __half* __restrict__ kh, const __half* __restrict__ vg,
        int kt, int slot, uint32_t sbase, int tid) {
    #pragma unroll
    for (int i = 0; i < 2; i++) {
        const int idx = (i << 8) + tid;
        const int r = idx >> 3, q = idx & 7;
        const int row = (kt << 6) + r;
        const uint32_t dK = sbase + Q_BYTES + slot * KV_SLOT + r * 144 + (q << 4);
        cp16(dK,                kh + (size_t)row * 64  + (q << 3));
        cp16(dK + 3 * KV_SLOT,  vg + (size_t)row * W1N + (q << 3));
    }
    cp_commit();
}

__global__ void __launch_bounds__(256, 2) attn_tc(
        const __half* __restrict__ qh, const __half* __restrict__ kh,
        const __half* __restrict__ h, __half* __restrict__ y) {
    extern __shared__ char smc[];
    __half* const smh = (__half*)smc;
    const uint32_t sbase = smem_u32(smc);

    const int tid  = threadIdx.x;
    const int warp = tid >> 5;
    const int lane = tid & 31;
    const int g = lane >> 2, t = lane & 3;
    const int bh = blockIdx.y;
    const int b = bh >> 4, hd = bh & 15;
    const int q0 = blockIdx.x << 7;

    const __half* qb = qh + (size_t)bh * LL * HEAD_DIM;
    const __half* kb = kh + (size_t)bh * LL * HEAD_DIM;
    const __half* vg = h + (size_t)b * LL * W1N + 2 * HIDDEN + hd * HEAD_DIM;

    const int rK = (lane & 7) + (lane >> 4) * 8;
    const int cK = ((lane >> 3) & 1) * 8;
    const int rV = (lane & 7) + ((lane >> 3) & 1) * 8;
    const int cV = (lane >> 4) * 8;
    const uint32_t koff = (rK * PQ + cK) * 2;
    const uint32_t voff = (rV * PQ + cV) * 2;

    #pragma unroll
    for (int i = 0; i < 4; i++) {
        int idx = (i << 8) + tid;
        int r = idx >> 3, q = idx & 7;
        *(uint4*)(smh + r * PQ + (q << 3)) =
            *(const uint4*)(qb + (size_t)(q0 + r) * 64 + (q << 3));
    }
    __syncthreads();
    uint32_t qa[4][4];
    {
        const uint32_t qoff = (((warp << 4) + rV) * PQ + cV) * 2;
        #pragma unroll
        for (int kk = 0; kk < 4; kk++)
            ldm_x4(qa[kk], sbase + qoff + ((kk * 16) << 1));
    }
    __syncthreads();

    float o[8][4];
    #pragma unroll
    for (int dn = 0; dn < 8; dn++)
        #pragma unroll
        for (int e = 0; e < 4; e++) o[dn][e] = 0.0f;
    float m0 = -1e30f, m1 = -1e30f, l0 = 0.0f, l1 = 0.0f;

    attn_issue_kv(kb, vg, 0, 0, sbase, tid);
    attn_issue_kv(kb, vg, 1, 1, sbase, tid);

    const int NT = LL / 64;
    int cur = 0, nxt = 2;
    for (int kt = 0; kt < NT; kt++) {
        if (kt + 1 < NT) cp_wait<1>(); else cp_wait<0>();
        __syncthreads();
        if (kt + 2 < NT)
            attn_issue_kv(kb, vg, kt + 2, nxt, sbase, tid);

        const uint32_t sK_b = sbase + Q_BYTES + cur * KV_SLOT;
        const uint32_t sV_b = sK_b + 3 * KV_SLOT;
        cur = (cur + 1 == 3) ? 0 : cur + 1;
        nxt = (nxt + 1 == 3) ? 0 : nxt + 1;

        float s[8][4];
        #pragma unroll
        for (int nt = 0; nt < 8; nt++)
            #pragma unroll
            for (int e = 0; e < 4; e++) s[nt][e] = 0.0f;
        #pragma unroll
        for (int kk = 0; kk < 4; kk++) {
            uint32_t kf[8][2];
            #pragma unroll
            for (int ntp = 0; ntp < 4; ntp++) {
                uint32_t tmp[4];
                ldm_x4(tmp, sK_b + koff + ((ntp * 16 * PQ + kk * 16) << 1));
                kf[2*ntp][0]   = tmp[0]; kf[2*ntp][1]   = tmp[1];
                kf[2*ntp+1][0] = tmp[2]; kf[2*ntp+1][1] = tmp[3];
            }
            #pragma unroll
            for (int nt = 0; nt < 8; nt++)
                mma_f16(s[nt], qa[kk], kf[nt]);
        }

        float mx0 = -1e30f, mx1 = -1e30f;
        #pragma unroll
        for (int nt = 0; nt < 8; nt++) {
            mx0 = fmaxf(mx0, fmaxf(s[nt][0], s[nt][1]));
            mx1 = fmaxf(mx1, fmaxf(s[nt][2], s[nt][3]));
        }
        mx0 = fmaxf(mx0, __shfl_xor_sync(0xffffffffu, mx0, 1));
        mx0 = fmaxf(mx0, __shfl_xor_sync(0xffffffffu, mx0, 2));
        mx1 = fmaxf(mx1, __shfl_xor_sync(0xffffffffu, mx1, 1));
        mx1 = fmaxf(mx1, __shfl_xor_sync(0xffffffffu, mx1, 2));
        const float M0 = fmaxf(m0, mx0), M1 = fmaxf(m1, mx1);
        const float f0 = __expf(m0 - M0), f1 = __expf(m1 - M1);
        m0 = M0; m1 = M1;

        float sum0 = 0.0f, sum1 = 0.0f;
        #pragma unroll
        for (int nt = 0; nt < 8; nt++) {
            s[nt][0] = __expf(s[nt][0] - M0);
            s[nt][1] = __expf(s[nt][1] - M0);
            s[nt][2] = __expf(s[nt][2] - M1);
            s[nt][3] = __expf(s[nt][3] - M1);
            sum0 += s[nt][0] + s[nt][1];
            sum1 += s[nt][2] + s[nt][3];
        }
        sum0 += __shfl_xor_sync(0xffffffffu, sum0, 1);
        sum0 += __shfl_xor_sync(0xffffffffu, sum0, 2);
        sum1 += __shfl_xor_sync(0xffffffffu, sum1, 1);
        sum1 += __shfl_xor_sync(0xffffffffu, sum1, 2);
        l0 = l0 * f0 + sum0;
        l1 = l1 * f1 + sum1;

        #pragma unroll
        for (int dn = 0; dn < 8; dn++) {
            o[dn][0] *= f0; o[dn][1] *= f0;
            o[dn][2] *= f1; o[dn][3] *= f1;
        }

        uint32_t pa[4][4];
        #pragma unroll
        for (int kc = 0; kc < 4; kc++) {
            pa[kc][0] = pack_f16(s[2*kc][0],   s[2*kc][1]);
            pa[kc][1] = pack_f16(s[2*kc][2],   s[2*kc][3]);
            pa[kc][2] = pack_f16(s[2*kc+1][0], s[2*kc+1][1]);
            pa[kc][3] = pack_f16(s[2*kc+1][2], s[2*kc+1][3]);
        }

        #pragma unroll
        for (int kc = 0; kc < 4; kc++) {
            #pragma unroll
            for (int dnp = 0; dnp < 4; dnp++) {
                uint32_t tmp[4];
                ldm_x4_t(tmp, sV_b + voff + ((kc * 16 * PQ + dnp * 16) << 1));
                mma_f16(o[2*dnp],   pa[kc], tmp);
                mma_f16(o[2*dnp+1], pa[kc], tmp + 2);
            }
        }
    }

    const float il0 = 1.0f / l0, il1 = 1.0f / l1;
    const int row0 = b * LL + q0 + (warp << 4) + g;
    __half* yp0 = y + (size_t)row0 * (2*HIDDEN) + hd * HEAD_DIM + (t << 1);
    __half* yp1 = yp0 + (size_t)8 * (2*HIDDEN);
    #pragma unroll
    for (int dn = 0; dn < 8; dn++) {
        *(uint32_t*)(yp0 + (dn << 3)) = pack_f16(o[dn][0] * il0, o[dn][1] * il0);
        *(uint32_t*)(yp1 + (dn << 3)) = pack_f16(o[dn][2] * il1, o[dn][3] * il1);
    }
}

// ---------------- mod GEMV: split-K(16) partial + reduce ------------------------
__global__ void __launch_bounds__(256) mod_partial(
        const float* __restrict__ vec, const float* __restrict__ w_mod,
        float* __restrict__ modp) {
    __shared__ float sv[64];
    const int b = blockIdx.z, ks = blockIdx.y;          // ks 0..15
    const int n = blockIdx.x * 256 + threadIdx.x;
    if (threadIdx.x < 64) {
        float v = vec[b * HIDDEN + ks * 64 + threadIdx.x];
        sv[threadIdx.x] = v / (1.0f + expf(-v));
    }
    __syncthreads();
    float acc = 0.0f;
    const float* W = w_mod + (size_t)(ks * 64) * (3 * HIDDEN) + n;
    #pragma unroll 8
    for (int k = 0; k < 64; k++)
        acc = fmaf(sv[k], W[(size_t)k * (3 * HIDDEN)], acc);
    modp[((ks * BB) + b) * (3 * HIDDEN) + n] = acc;
}

__global__ void __launch_bounds__(256) mod_reduce(
        const float* __restrict__ modp, const float* __restrict__ b_mod,
        float* __restrict__ mod) {
    const int idx = blockIdx.x * 256 + threadIdx.x;
    const int b = idx / (3 * HIDDEN), n = idx % (3 * HIDDEN);
    float s = b_mod[n];
    #pragma unroll
    for (int ks = 0; ks < 16; ks++)
        s += modp[((ks * BB) + b) * (3 * HIDDEN) + n];
    mod[idx] = s;
}

// ---------------- kernel 2: layernorm + modulate -> fp16 ------------------------
__global__ void __launch_bounds__(256) ln_mod_kernel(const float* __restrict__ x,
                                                     const float* __restrict__ mod,
                                                     __half* __restrict__ xmod) {
    __shared__ float sbuf[8];
    __shared__ float s_mean, s_rstd;
    int token = blockIdx.x;
    int b = token >> 11;
    int tid = threadIdx.x;
    const float4 xv = ((const float4*)(x + (size_t)token*HIDDEN))[tid];

    float s = xv.x + xv.y + xv.z + xv.w;
    #pragma unroll
    for (int o = 16; o > 0; o >>= 1) s += __shfl_xor_sync(0xffffffffu, s, o);
    if ((tid & 31) == 0) sbuf[tid >> 5] = s;
    __syncthreads();
    if (tid == 0) {
        float tq = 0;
        #pragma unroll
        for (int i = 0; i < 8; i++) tq += sbuf[i];
        s_mean = tq * (1.0f / HIDDEN);
    }
    __syncthreads();
    float m = s_mean;
    float dx = xv.x - m, dy = xv.y - m, dz = xv.z - m, dw = xv.w - m;
    float ss = dx*dx + dy*dy + dz*dz + dw*dw;
    #pragma unroll
    for (int o = 16; o > 0; o >>= 1) ss += __shfl_xor_sync(0xffffffffu, ss, o);
    __syncthreads();
    if ((tid & 31) == 0) sbuf[tid >> 5] = ss;
    __syncthreads();
    if (tid == 0) {
        float tq = 0;
        #pragma unroll
        for (int i = 0; i < 8; i++) tq += sbuf[i];
        s_rstd = rsqrtf(tq * (1.0f / HIDDEN) + 1e-6f);
    }
    __syncthreads();
    float r = s_rstd;
    int c = tid * 4;
    const float4 sh = *(const float4*)(mod + b*3*HIDDEN + c);
    const float4 sc = *(const float4*)(mod + b*3*HIDDEN + HIDDEN + c);
    float o0 = fmaf(1.0f + sc.x, dx*r, sh.x);
    float o1 = fmaf(1.0f + sc.y, dy*r, sh.y);
    float o2 = fmaf(1.0f + sc.z, dz*r, sh.z);
    float o3 = fmaf(1.0f + sc.w, dw*r, sh.w);
    uint32_t* dst = (uint32_t*)(xmod + (size_t)token*HIDDEN + c);
    dst[0] = pack_f16(o0, o1);
    dst[1] = pack_f16(o2, o3);
}

// ---------------- kernel 4: RMSNorm + RoPE, fp16 h -> per-head q/k ---------------
__global__ void __launch_bounds__(512) qk_norm_rope_kernel(
        const __half* __restrict__ h,
        const float* __restrict__ pe,
        const float* __restrict__ q_scale,
        const float* __restrict__ k_scale,
        __half* __restrict__ qh, __half* __restrict__ kh) {
    int token = blockIdx.x;
    int l = token & (LL - 1);
    int b = token >> 11;
    int head = threadIdx.x >> 5;
    int lane = threadIdx.x & 31;

    const __half* hq = h + (size_t)token*W1N + head*HEAD_DIM;
    const size_t oidx = ((size_t)(b*HEADS + head)*LL + l)*HEAD_DIM + lane*2;

    const float4 p = *(const float4*)(pe + (size_t)l*128 + lane*4);
    float sx = q_scale[lane*2], sy = q_scale[lane*2+1];
    float kx = k_scale[lane*2], ky = k_scale[lane*2+1];

    {
        float2 q2 = __half22float2(*(const __half2*)(hq + lane*2));
        float ss = q2.x*q2.x + q2.y*q2.y;
        #pragma unroll
        for (int o = 16; o > 0; o >>= 1) ss += __shfl_xor_sync(0xffffffffu, ss, o);
        float rr = rsqrtf(ss * (1.0f/HEAD_DIM) + 1e-6f);
        float t0 = q2.x * rr * sx, t1 = q2.y * rr * sy;
        *(uint32_t*)(qh + oidx) =
            pack_f16(0.125f*(p.x*t0 + p.y*t1), 0.125f*(p.z*t0 + p.w*t1));
    }
    {
        float2 k2 = __half22float2(*(const __half2*)(hq + HIDDEN + lane*2));
        float ss = k2.x*k2.x + k2.y*k2.y;
        #pragma unroll
        for (int o = 16; o > 0; o >>= 1) ss += __shfl_xor_sync(0xffffffffu, ss, o);
        float rr = rsqrtf(ss * (1.0f/HEAD_DIM) + 1e-6f);
        float t0 = k2.x * rr * kx, t1 = k2.y * rr * ky;
        *(uint32_t*)(kh + oidx) = pack_f16(p.x*t0 + p.y*t1, p.z*t0 + p.w*t1);
    }
}

// ---------------- launch --------------------------------------------------------
extern "C" void kernel_launch(void* const* d_in, const int* in_sizes, int n_in,
                              void* d_out, int out_size) {
    const float* x       = (const float*)d_in[0];
    const float* vec     = (const float*)d_in[1];
    const float* pe      = (const float*)d_in[2];
    const float* w_mod   = (const float*)d_in[3];
    const float* b_mod   = (const float*)d_in[4];
    const float* w1      = (const float*)d_in[5];
    const float* b1      = (const float*)d_in[6];
    const float* w_mlp   = (const float*)d_in[7];
    const float* b_mlp   = (const float*)d_in[8];
    const float* w2      = (const float*)d_in[9];
    const float* b2      = (const float*)d_in[10];
    const float* q_scale = (const float*)d_in[11];
    const float* k_scale = (const float*)d_in[12];
    float* out = (float*)d_out;

    float *mod, *modp;
    __half *xmod, *h, *qh, *kh, *y, *w1t, *wmlpt, *w2t;
    cudaGetSymbolAddress((void**)&mod,   g_mod);
    cudaGetSymbolAddress((void**)&modp,  g_modp);
    cudaGetSymbolAddress((void**)&xmod,  g_xmod);
    cudaGetSymbolAddress((void**)&h,     g_h);
    cudaGetSymbolAddress((void**)&qh,    g_qh);
    cudaGetSymbolAddress((void**)&kh,    g_kh);
    cudaGetSymbolAddress((void**)&y,     g_y);
    cudaGetSymbolAddress((void**)&w1t,   g_w1t);
    cudaGetSymbolAddress((void**)&wmlpt, g_wmlpt);
    cudaGetSymbolAddress((void**)&w2t,   g_w2t);

    static cudaStream_t s1 = nullptr;
    static cudaEvent_t evF = nullptr, evW1 = nullptr, evH = nullptr, evMLP = nullptr;
    if (!s1) {
        cudaStreamCreateWithFlags(&s1, cudaStreamNonBlocking);
        cudaEventCreateWithFlags(&evF,   cudaEventDisableTiming);
        cudaEventCreateWithFlags(&evW1,  cudaEventDisableTiming);
        cudaEventCreateWithFlags(&evH,   cudaEventDisableTiming);
        cudaEventCreateWithFlags(&evMLP, cudaEventDisableTiming);
        cudaFuncSetAttribute(mma_gemm<0>, cudaFuncAttributeMaxDynamicSharedMemorySize, GEMM_SMEM);
        cudaFuncSetAttribute(mma_gemm<1>, cudaFuncAttributeMaxDynamicSharedMemorySize, GEMM_SMEM);
        cudaFuncSetAttribute(mma_gemm<2>, cudaFuncAttributeMaxDynamicSharedMemorySize, GEMM_SMEM);
        cudaFuncSetAttribute(attn_tc,     cudaFuncAttributeMaxDynamicSharedMemorySize, ATTN_SMEM);
    }

    // fork side stream from main (legacy) stream
    cudaEventRecord(evF, 0);
    cudaStreamWaitEvent(s1, evF, 0);

    // side: weight transposes (w1t first; it gates GEMM0)
    transpose_h<<<dim3(W1N/32, HIDDEN/32), dim3(32,8), 0, s1>>>(w1, w1t, HIDDEN, W1N);
    cudaEventRecord(evW1, s1);
    transpose_h<<<dim3(HIDDEN/32, MLPH/32),     dim3(32,8), 0, s1>>>(w_mlp, wmlpt, MLPH,     HIDDEN);
    transpose_h<<<dim3(HIDDEN/32, 2*HIDDEN/32), dim3(32,8), 0, s1>>>(w2,    w2t,   2*HIDDEN, HIDDEN);

    // main: modulation + layernorm (concurrent with transposes)
    mod_partial<<<dim3(3*HIDDEN/256, 16, BB), 256>>>(vec, w_mod, modp);
    mod_reduce<<<BB*3*HIDDEN/256, 256>>>(modp, b_mod, mod);
    ln_mod_kernel<<<NTOK, 256>>>(x, mod, xmod);

    // main: GEMM0 (needs xmod + w1t)
    cudaStreamWaitEvent(0, evW1, 0);
    mma_gemm<0><<<dim3(W1N/128, NTOK/128), 256, GEMM_SMEM>>>(
        xmod, HIDDEN, w1t, HIDDEN, h, W1N, HIDDEN, b1, nullptr, nullptr);
    cudaEventRecord(evH, 0);

    // side: MLP GEMM (needs h + wmlpt), overlaps rope+attn on main
    cudaStreamWaitEvent(s1, evH, 0);
    mma_gemm<1><<<dim3(HIDDEN/128, NTOK/128), 256, GEMM_SMEM, s1>>>(
        h + 3*HIDDEN, W1N, wmlpt, MLPH, y + HIDDEN, 2*HIDDEN,
        MLPH, b_mlp, nullptr, nullptr);
    cudaEventRecord(evMLP, s1);

    // main: rope + attention (V read directly from h inside attn)
    qk_norm_rope_kernel<<<NTOK, 512>>>(h, pe, q_scale, k_scale, qh, kh);
    attn_tc<<<dim3(LL/128, BB*HEADS), 256, ATTN_SMEM>>>(qh, kh, h, y);

    // join, final GEMM
    cudaStreamWaitEvent(0, evMLP, 0);
    mma_gemm<2><<<dim3(HIDDEN/128, NTOK/128), 256, GEMM_SMEM>>>(
        y, 2*HIDDEN, w2t, 2*HIDDEN, out, HIDDEN,
        2*HIDDEN, b2, x, mod);
}